// round 2
// baseline (speedup 1.0000x reference)
#include <cuda_runtime.h>
#include <math.h>

// Problem dims
#define NN   2000   // nodes
#define NE   3000   // edges
#define BB   16     // batch
#define CC   17     // dim_in
#define WW   12     // window
#define DD   16     // embed
#define OO   256    // dim_out
#define KK   3      // link len
#define NBB  3      // bootstrap
#define BC   (BB*CC)    // 272
#define NCP  320        // padded cols for GEMM (multiple of 64)
#define KCQ  (KK*CC)    // 51
#define O4   64
#define O8   32
#define O2   128

// ---------------- scratch (device globals; no runtime alloc) ----------------
__device__ float g_S[NN*NN];          // 16 MB
__device__ float g_rrow[NN];          // reciprocal row sums
__device__ float g_Xt[NN*NCP];
__device__ float g_Y1[NN*NCP];
__device__ float g_Y2[NN*NCP];
__device__ float g_W[NN*KCQ*O4];      // 26 MB adaptive weights
__device__ float g_bias[NN*OO];
__device__ float g_wws[NN*O8];
__device__ float g_wwt[NN*O2];
__device__ float g_xw[BB*NN];
__device__ float g_se[BB*NE];
__device__ float g_te[BB*NE];
__device__ float g_mpT[NE*BB];        // transposed (e,b)
__device__ float g_xm[NN*BB];         // (n,b)
__device__ float g_rsum[NN];

// Robust scalar decode: harness may pass python-int scalars as int32 or float32.
// Small-magnitude int bit pattern -> int; otherwise reinterpret as float.
__device__ __forceinline__ float decode_scalar(const int* p) {
    int iv = *p;
    return (iv > -1000000 && iv < 1000000) ? (float)iv : __int_as_float(iv);
}

// ---------------- S0 = relu(ne@ne^T), diag=stay ----------------
__global__ void kS0(const float* __restrict__ ne, const int* __restrict__ stay) {
    __shared__ float nei[32][17], nej[32][17];
    int i0 = blockIdx.y * 32, j0 = blockIdx.x * 32;
    int t = threadIdx.x;
    for (int l = t; l < 32 * 16; l += 256) {
        int r = l >> 4, d = l & 15;
        nei[r][d] = (i0 + r < NN) ? ne[(i0 + r) * DD + d] : 0.f;
        nej[r][d] = (j0 + r < NN) ? ne[(j0 + r) * DD + d] : 0.f;
    }
    __syncthreads();
    float sc = decode_scalar(stay);
    for (int l = t; l < 1024; l += 256) {
        int ri = l >> 5, rj = l & 31;
        int i = i0 + ri, j = j0 + rj;
        if (i < NN && j < NN) {
            float acc = 0.f;
#pragma unroll
            for (int d = 0; d < 16; d++) acc += nei[ri][d] * nej[rj][d];
            g_S[i * NN + j] = (i == j) ? sc : fmaxf(acc, 0.f);
        }
    }
}

// ---------------- per-row softmax (or adj*exp for fixed branch) ----------------
__global__ void kSoftmax(const float* __restrict__ adj, const int* __restrict__ fixedp) {
    __shared__ float row[NN];
    __shared__ float red[256];
    int i = blockIdx.x, t = threadIdx.x;
    int isfixed = (decode_scalar(fixedp) != 0.0f);
    float mx = -1e30f;
    for (int j = t; j < NN; j += 256) { float v = g_S[i * NN + j]; row[j] = v; mx = fmaxf(mx, v); }
    red[t] = mx; __syncthreads();
    for (int s = 128; s > 0; s >>= 1) { if (t < s) red[t] = fmaxf(red[t], red[t + s]); __syncthreads(); }
    mx = red[0]; __syncthreads();
    float sum = 0.f;
    if (!isfixed) {
        for (int j = t; j < NN; j += 256) { float e = expf(row[j] - mx); row[j] = e; sum += e; }
    } else {
        for (int j = t; j < NN; j += 256) { float e = adj[i * NN + j] * expf(row[j]); row[j] = e; sum += e; }
    }
    red[t] = sum; __syncthreads();
    for (int s = 128; s > 0; s >>= 1) { if (t < s) red[t] += red[t + s]; __syncthreads(); }
    sum = red[0];
    if (!isfixed) {
        float inv = 1.f / sum;
        for (int j = t; j < NN; j += 256) g_S[i * NN + j] = row[j] * inv;
    } else {
        for (int j = t; j < NN; j += 256) g_S[i * NN + j] = row[j];
    }
}

// ---------------- rowsum reciprocals of current S ----------------
__global__ void kRowsumS() {
    __shared__ float red[256];
    int i = blockIdx.x, t = threadIdx.x;
    float s = 0.f;
    for (int j = t; j < NN; j += 256) s += g_S[(size_t)i * NN + j];
    red[t] = s; __syncthreads();
    for (int st = 128; st > 0; st >>= 1) { if (t < st) red[t] += red[t + st]; __syncthreads(); }
    if (t == 0) g_rrow[i] = 1.f / red[0];
}

// column j multiplied by 1/rowsum[j] (exact reference semantics, both branches)
__global__ void kColDiv() {
    int idx = blockIdx.x * blockDim.x + threadIdx.x;
    int stride = gridDim.x * blockDim.x;
    for (; idx < NN * NN; idx += stride) {
        int j = idx % NN;
        g_S[idx] *= g_rrow[j];
    }
}

// ---------------- pack x (B,N,C) -> Xt (N, NCP) zero-padded ----------------
__global__ void kPack(const float* __restrict__ x) {
    int idx = blockIdx.x * blockDim.x + threadIdx.x;
    int stride = gridDim.x * blockDim.x;
    for (; idx < NN * NCP; idx += stride) {
        int m = idx / NCP, col = idx % NCP;
        float v = 0.f;
        if (col < BC) { int b = col / CC, c = col % CC; v = x[(b * NN + m) * CC + c]; }
        g_Xt[idx] = v;
    }
}

// ---------------- fp32 SGEMM: C(2000,320) = S(2000,2000) @ B(2000,320) ----------------
// phase 0: B=g_Xt -> C=g_Y1 ; phase 1: B=g_Y1 -> C=g_Y2
// (globals referenced ONLY in device code — host-passed __device__ symbols are
//  silently wrong on GB300 because ATS makes the host shadow readable)
__global__ __launch_bounds__(256) void kGemm(int phase) {
    const float* __restrict__ B = phase ? g_Y1 : g_Xt;
    float* __restrict__ Cout    = phase ? g_Y2 : g_Y1;
    __shared__ float As[16][68];
    __shared__ float Bs[16][68];
    int t = threadIdx.x;
    int tx = t & 15, ty = t >> 4;
    int m0 = blockIdx.x * 64, n0 = blockIdx.y * 64;
    float acc[4][4] = {};
    int a_m = t >> 2;
    int a_k4 = (t & 3) * 4;
    int b_k = t >> 4;
    int b_n4 = (t & 15) * 4;
    bool arow_ok = (m0 + a_m) < NN;
    const float* Aptr = g_S + (size_t)(m0 + a_m) * NN + a_k4;
    const float* Bptr = B + (size_t)b_k * NCP + n0 + b_n4;

    float4 av = arow_ok ? *(const float4*)(Aptr) : make_float4(0, 0, 0, 0);
    float4 bv = *(const float4*)(Bptr);

    for (int kb = 0; kb < NN / 16; kb++) {
        As[a_k4 + 0][a_m] = av.x; As[a_k4 + 1][a_m] = av.y;
        As[a_k4 + 2][a_m] = av.z; As[a_k4 + 3][a_m] = av.w;
        *(float4*)&Bs[b_k][b_n4] = bv;
        __syncthreads();
        if (kb + 1 < NN / 16) {
            av = arow_ok ? *(const float4*)(Aptr + (kb + 1) * 16) : make_float4(0, 0, 0, 0);
            bv = *(const float4*)(Bptr + (size_t)(kb + 1) * 16 * NCP);
        }
#pragma unroll
        for (int kk = 0; kk < 16; kk++) {
            float4 a = *(const float4*)&As[kk][ty * 4];
            float4 b = *(const float4*)&Bs[kk][tx * 4];
            acc[0][0] += a.x * b.x; acc[0][1] += a.x * b.y; acc[0][2] += a.x * b.z; acc[0][3] += a.x * b.w;
            acc[1][0] += a.y * b.x; acc[1][1] += a.y * b.y; acc[1][2] += a.y * b.z; acc[1][3] += a.y * b.w;
            acc[2][0] += a.z * b.x; acc[2][1] += a.z * b.y; acc[2][2] += a.z * b.z; acc[2][3] += a.z * b.w;
            acc[3][0] += a.w * b.x; acc[3][1] += a.w * b.y; acc[3][2] += a.w * b.z; acc[3][3] += a.w * b.w;
        }
        __syncthreads();
    }
#pragma unroll
    for (int i = 0; i < 4; i++) {
        int r = m0 + ty * 4 + i;
        if (r < NN)
            *(float4*)&Cout[(size_t)r * NCP + n0 + tx * 4] =
                make_float4(acc[i][0], acc[i][1], acc[i][2], acc[i][3]);
    }
}

// ---------------- adaptive weights: W[n,kc,o] = sum_d ne[n,d] wp[d,kc,o] ----------------
__global__ void kWeights(const float* __restrict__ ne, const float* __restrict__ wp) {
    __shared__ float nes[32][17];
    int j0 = blockIdx.x * 256;
    int n0 = blockIdx.y * 32;
    int t = threadIdx.x;
    for (int l = t; l < 32 * 16; l += 256) {
        int r = l >> 4, d = l & 15;
        nes[r][d] = (n0 + r < NN) ? ne[(n0 + r) * DD + d] : 0.f;
    }
    __syncthreads();
    int j = j0 + t;
    if (j < KCQ * O4) {
        float w[16];
#pragma unroll
        for (int d = 0; d < 16; d++) w[d] = wp[d * (KCQ * O4) + j];
        for (int r = 0; r < 32; r++) {
            int n = n0 + r;
            if (n >= NN) break;
            float acc = 0.f;
#pragma unroll
            for (int d = 0; d < 16; d++) acc += nes[r][d] * w[d];
            g_W[(size_t)n * (KCQ * O4) + j] = acc;
        }
    }
}

// ---------------- bias / wws / wwt ----------------
__global__ void kSmall(const float* __restrict__ ne, const float* __restrict__ bp,
                       const float* __restrict__ wwsp, const float* __restrict__ wwtp) {
    __shared__ float nn[16];
    int n = blockIdx.x, t = threadIdx.x;
    if (t < 16) nn[t] = ne[n * DD + t];
    __syncthreads();
    float acc = 0.f;
#pragma unroll
    for (int d = 0; d < 16; d++) acc += nn[d] * bp[d * OO + t];
    g_bias[n * OO + t] = acc;
    if (t < O8) {
        float a = 0.f;
#pragma unroll
        for (int d = 0; d < 16; d++) a += nn[d] * wwsp[d * O8 + t];
        g_wws[n * O8 + t] = a;
    }
    if (t < O2) {
        float a = 0.f;
#pragma unroll
        for (int d = 0; d < 16; d++) a += nn[d] * wwtp[d * O2 + t];
        g_wwt[n * O2 + t] = a;
    }
}

// ---------------- rsum[m] = sum_n gnn_w[m,n] ----------------
__global__ void kRsum(const float* __restrict__ gw) {
    __shared__ float red[128];
    int m = blockIdx.x, t = threadIdx.x;
    float s = 0.f;
    for (int j = t; j < NN; j += 128) s += gw[(size_t)m * NN + j];
    red[t] = s; __syncthreads();
    for (int st = 64; st > 0; st >>= 1) { if (t < st) red[t] += red[t + st]; __syncthreads(); }
    if (t == 0) g_rsum[m] = red[0];
}

// ---------------- temporal window reduce ----------------
__global__ void kXw(const float* __restrict__ xwin, const float* __restrict__ Tp) {
    int idx = blockIdx.x * blockDim.x + threadIdx.x;
    if (idx >= BB * NN) return;
    int b = idx / NN, n = idx % NN;
    float s = 0.f;
#pragma unroll
    for (int t = 0; t < WW; t++) s += xwin[(size_t)b * WW * NN + t * NN + n] * Tp[t];
    g_xw[idx] = s;
}

// ---------------- hodge branch: se/te ----------------
__global__ void kH1(const float* __restrict__ xew, const int* __restrict__ bidx,
                    const float* __restrict__ lw, const float* __restrict__ lb) {
    int idx = blockIdx.x * blockDim.x + threadIdx.x;
    if (idx >= BB * NE) return;
    int b = idx / NE, i = idx % NE;
    float w0 = lw[0], b0 = lb[0];
    float s = 0.f, tt = 0.f;
#pragma unroll
    for (int f = 0; f < NBB; f++) {
        int wv = bidx[f];
        float v = xew[(size_t)b * WW * NE + (size_t)wv * NE + i] * w0 + b0;
        s += v;
        tt += (float)(NBB - 1 - f) * v;
    }
    g_se[idx] = s;
    g_te[idx] = tt;
}

__global__ void kH2init(const int* __restrict__ jumpp) {
    int idx = blockIdx.x * blockDim.x + threadIdx.x;
    if (idx >= NE * BB) return;
    int e = idx / BB, b = idx % BB;
    g_mpT[idx] = decode_scalar(jumpp) * g_te[b * NE + e];
}

__global__ void kH2(const float* __restrict__ hodge) {
    __shared__ float ses[16][251];
    int j0 = blockIdx.x * 128;
    int i0 = blockIdx.y * 250;
    int t = threadIdx.x;
    for (int l = t; l < 16 * 250; l += 128) {
        int b = l / 250, ii = l % 250;
        ses[b][ii] = g_se[b * NE + i0 + ii];
    }
    __syncthreads();
    int j = j0 + t;
    if (j < NE) {
        float acc[16] = {};
        for (int ii = 0; ii < 250; ii++) {
            float h = hodge[(size_t)(i0 + ii) * NE + j];
#pragma unroll
            for (int b = 0; b < 16; b++) acc[b] += ses[b][ii] * h;
        }
#pragma unroll
        for (int b = 0; b < 16; b++) atomicAdd(&g_mpT[j * BB + b], acc[b]);
    }
}

// xm[n,b] = (1/nb) sum_e mpT[e,b] * inc[n,e]
__global__ void kH3(const float* __restrict__ inc, int nb) {
    __shared__ float incs[16][65];
    __shared__ float mps[64][17];
    int n0 = blockIdx.x * 16;
    int t = threadIdx.x;
    int nr = t >> 4, b = t & 15;
    float acc = 0.f;
    for (int e0 = 0; e0 < NE; e0 += 64) {
        for (int l = t; l < 1024; l += 256) {
            int r = l >> 6, ee = l & 63;
            int e = e0 + ee;
            incs[r][ee] = (e < NE) ? inc[(size_t)(n0 + r) * NE + e] : 0.f;
        }
        for (int l = t; l < 1024; l += 256) {
            int ee = l >> 4, bb = l & 15;
            int e = e0 + ee;
            mps[ee][bb] = (e < NE) ? g_mpT[e * BB + bb] : 0.f;
        }
        __syncthreads();
#pragma unroll 8
        for (int ee = 0; ee < 64; ee++) acc += incs[nr][ee] * mps[ee][b];
        __syncthreads();
    }
    g_xm[(n0 + nr) * BB + b] = acc / (float)nb;
}

// ---------------- diffusion epilogue: out[:, :, 0:64] ----------------
__global__ __launch_bounds__(256) void kF1(const float* __restrict__ x, float* __restrict__ out) {
    __shared__ float ws[KCQ * O4];         // 13 KB
    __shared__ float xs[BB][KCQ + 1];
    int n = blockIdx.x, t = threadIdx.x;
    for (int l = t; l < KCQ * O4; l += 256) ws[l] = g_W[(size_t)n * (KCQ * O4) + l];
    for (int l = t; l < BB * KCQ; l += 256) {
        int b = l / KCQ, kc = l % KCQ;
        int k = kc / CC, c = kc % CC;
        float v;
        if (k == 0)      v = x[(size_t)(b * NN + n) * CC + c];
        else if (k == 1) v = g_Y1[(size_t)n * NCP + b * CC + c];
        else             v = g_Y2[(size_t)n * NCP + b * CC + c];
        xs[b][kc] = v;
    }
    __syncthreads();
    int o = t & 63, bq = t >> 6;
    int b0 = bq * 4;
    float a0 = 0.f, a1 = 0.f, a2 = 0.f, a3 = 0.f;
    for (int kc = 0; kc < KCQ; kc++) {
        float w = ws[kc * O4 + o];
        a0 += xs[b0 + 0][kc] * w;
        a1 += xs[b0 + 1][kc] * w;
        a2 += xs[b0 + 2][kc] * w;
        a3 += xs[b0 + 3][kc] * w;
    }
    float bi = g_bias[n * OO + o];
    out[(size_t)((b0 + 0) * NN + n) * OO + o] = a0 + bi;
    out[(size_t)((b0 + 1) * NN + n) * OO + o] = a1 + bi;
    out[(size_t)((b0 + 2) * NN + n) * OO + o] = a2 + bi;
    out[(size_t)((b0 + 3) * NN + n) * OO + o] = a3 + bi;
}

// ---------------- ZFC + temporal + supra epilogues: out[:, :, 64:256] ----------------
__global__ void kFrest(const float* __restrict__ zin, const float* __restrict__ gnnb,
                       float* __restrict__ out) {
    int bx = blockIdx.x;
    int n = bx % NN, b = bx / NN;
    int j = threadIdx.x;   // 0..191
    float v; int o;
    if (j < 32) {
        int k = n * 32 + j;
        int q = k / NN;
        int m = k - q * NN;
        v = fmaxf(zin[b * 32 + q] * g_rsum[m] + gnnb[m], 0.f);
        o = 64 + j;
    } else if (j < 160) {
        int jj = j - 32;
        v = g_xw[b * NN + n] * g_wwt[n * O2 + jj];
        o = 96 + jj;
    } else {
        int jj = j - 160;
        v = g_xm[n * BB + b] * g_wws[n * O8 + jj];
        o = 224 + jj;
    }
    out[(size_t)(b * NN + n) * OO + o] = v + g_bias[n * OO + o];
}

// ---------------- launch ----------------
extern "C" void kernel_launch(void* const* d_in, const int* in_sizes, int n_in,
                              void* d_out, int out_size) {
    const float* x     = (const float*)d_in[0];
    const float* xwin  = (const float*)d_in[1];
    const float* ne    = (const float*)d_in[2];
    const int*   fixed = (const int*)  d_in[3];
    const float* adj   = (const float*)d_in[4];
    const int*   stay  = (const int*)  d_in[5];
    const int*   jump  = (const int*)  d_in[6];
    const float* zin   = (const float*)d_in[7];
    const float* hodge = (const float*)d_in[8];
    const float* xew   = (const float*)d_in[9];
    const float* inc   = (const float*)d_in[10];
    const float* wp    = (const float*)d_in[11];
    const float* wwsp  = (const float*)d_in[12];
    const float* wwtp  = (const float*)d_in[13];
    const float* bp    = (const float*)d_in[14];
    const float* Tp    = (const float*)d_in[15];
    const float* lw    = (const float*)d_in[16];
    const float* lb    = (const float*)d_in[17];
    const float* gw    = (const float*)d_in[18];
    const float* gnnb  = (const float*)d_in[19];
    const int*   bidx  = (const int*)  d_in[20];
    float* out = (float*)d_out;
    int nb = in_sizes[20];   // NB = 3

    // adjacency / transition matrix
    kS0<<<dim3(63, 63), 256>>>(ne, stay);
    kSoftmax<<<NN, 256>>>(adj, fixed);
    kRowsumS<<<NN, 256>>>();
    kColDiv<<<512, 256>>>();

    // diffusion GEMMs (device globals referenced inside kernel, NOT passed from host)
    kPack<<<2500, 256>>>(x);
    kGemm<<<dim3(32, 5), 256>>>(0);
    kGemm<<<dim3(32, 5), 256>>>(1);

    // adaptive params
    kWeights<<<dim3(13, 63), 256>>>(ne, wp);
    kSmall<<<NN, 256>>>(ne, bp, wwsp, wwtp);

    // ZFC / temporal
    kRsum<<<NN, 128>>>(gw);
    kXw<<<(BB * NN + 255) / 256, 256>>>(xwin, Tp);

    // hodge / supra branch
    kH1<<<(BB * NE + 255) / 256, 256>>>(xew, bidx, lw, lb);
    kH2init<<<(NE * BB + 255) / 256, 256>>>(jump);
    kH2<<<dim3(24, 12), 128>>>(hodge);
    kH3<<<125, 256>>>(inc, nb);

    // output assembly
    kF1<<<NN, 256>>>(x, out);
    kFrest<<<BB * NN, 192>>>(zin, gnnb, out);
}

// round 4
// speedup vs baseline: 1.3912x; 1.3912x over previous
#include <cuda_runtime.h>
#include <cuda_bf16.h>
#include <math.h>

// Problem dims
#define NN   2000   // nodes
#define NE   3000   // edges
#define BB   16     // batch
#define CC   17     // dim_in
#define WW   12     // window
#define DD   16     // embed
#define OO   256    // dim_out
#define KK   3      // link len
#define NBB  3      // bootstrap
#define BC   (BB*CC)    // 272
#define NCP  320        // fp32 Y stride
#define KPAD 2048       // bf16 padded k-stride (zero-init padding)
#define KCQ  (KK*CC)    // 51
#define O4   64
#define O8   32
#define O2   128

// ---------------- scratch (device globals; no runtime alloc) ----------------
__device__ float g_S[NN*NN];                 // fp32 S0 / fixed-path S (16 MB)
__device__ __nv_bfloat16 g_Sh[NN*KPAD];      // bf16 S, rows m, cols k (8 MB, pad zero)
__device__ __nv_bfloat16 g_XtT[NCP*KPAD];    // bf16 X^T: rows n=b*17+c, cols m
__device__ __nv_bfloat16 g_Y1T[NCP*KPAD];    // bf16 Y1^T for GEMM2
__device__ float g_rrow[NN];
__device__ float g_Y1[NN*NCP];
__device__ float g_Y2[NN*NCP];
__device__ float g_W[NN*KCQ*O4];             // adaptive weights
__device__ float g_bias[NN*OO];
__device__ float g_wws[NN*O8];
__device__ float g_wwt[NN*O2];
__device__ float g_xw[BB*NN];
__device__ float g_se[BB*NE];
__device__ float g_te[BB*NE];
__device__ float g_mpT[NE*BB];
__device__ float g_xm[NN*BB];
__device__ float g_rsum[NN];

__device__ __forceinline__ float decode_scalar(const int* p) {
    int iv = *p;
    return (iv > -1000000 && iv < 1000000) ? (float)iv : __int_as_float(iv);
}

// ---------------- S0 = relu(ne@ne^T), diag=stay ----------------
__global__ void kS0(const float* __restrict__ ne, const int* __restrict__ stay) {
    __shared__ float nei[32][17], nej[32][17];
    int i0 = blockIdx.y * 32, j0 = blockIdx.x * 32;
    int t = threadIdx.x;
    for (int l = t; l < 32 * 16; l += 256) {
        int r = l >> 4, d = l & 15;
        nei[r][d] = (i0 + r < NN) ? ne[(i0 + r) * DD + d] : 0.f;
        nej[r][d] = (j0 + r < NN) ? ne[(j0 + r) * DD + d] : 0.f;
    }
    __syncthreads();
    float sc = decode_scalar(stay);
    for (int l = t; l < 1024; l += 256) {
        int ri = l >> 5, rj = l & 31;
        int i = i0 + ri, j = j0 + rj;
        if (i < NN && j < NN) {
            float acc = 0.f;
#pragma unroll
            for (int d = 0; d < 16; d++) acc += nei[ri][d] * nej[rj][d];
            g_S[i * NN + j] = (i == j) ? sc : fmaxf(acc, 0.f);
        }
    }
}

// ---------------- softmax row -> bf16 S directly (softmax path) ----------------
// fixed path: writes adj*exp into g_S; normalization handled by kRowsumS/kColDivH.
__global__ void kSoftmax(const float* __restrict__ adj, const int* __restrict__ fixedp) {
    __shared__ float row[NN];
    __shared__ float red[256];
    int i = blockIdx.x, t = threadIdx.x;
    int isfixed = (decode_scalar(fixedp) != 0.0f);
    float mx = -1e30f;
    for (int j = t; j < NN; j += 256) { float v = g_S[(size_t)i * NN + j]; row[j] = v; mx = fmaxf(mx, v); }
    red[t] = mx; __syncthreads();
    for (int s = 128; s > 0; s >>= 1) { if (t < s) red[t] = fmaxf(red[t], red[t + s]); __syncthreads(); }
    mx = red[0]; __syncthreads();
    float sum = 0.f;
    if (!isfixed) {
        for (int j = t; j < NN; j += 256) { float e = expf(row[j] - mx); row[j] = e; sum += e; }
    } else {
        for (int j = t; j < NN; j += 256) { float e = adj[(size_t)i * NN + j] * expf(row[j]); row[j] = e; sum += e; }
    }
    red[t] = sum; __syncthreads();
    for (int s = 128; s > 0; s >>= 1) { if (t < s) red[t] += red[t + s]; __syncthreads(); }
    sum = red[0];
    if (!isfixed) {
        // post-softmax rowsum == 1 to ~6e-7; the column division is a no-op at
        // our error budget -> emit normalized bf16 S directly.
        float inv = 1.f / sum;
        for (int j = t; j < NN; j += 256)
            g_Sh[(size_t)i * KPAD + j] = __float2bfloat16(row[j] * inv);
    } else {
        for (int j = t; j < NN; j += 256) g_S[(size_t)i * NN + j] = row[j];
    }
}

// ---------------- fixed-adj-only: rowsums + column normalize -> bf16 ----------------
__global__ void kRowsumS(const int* __restrict__ fixedp) {
    if (decode_scalar(fixedp) == 0.0f) return;
    __shared__ float red[256];
    int i = blockIdx.x, t = threadIdx.x;
    float s = 0.f;
    for (int j = t; j < NN; j += 256) s += g_S[(size_t)i * NN + j];
    red[t] = s; __syncthreads();
    for (int st = 128; st > 0; st >>= 1) { if (t < st) red[t] += red[t + st]; __syncthreads(); }
    if (t == 0) g_rrow[i] = 1.f / red[0];
}

__global__ void kColDivH(const int* __restrict__ fixedp) {
    if (decode_scalar(fixedp) == 0.0f) return;
    int idx = blockIdx.x * blockDim.x + threadIdx.x;
    int stride = gridDim.x * blockDim.x;
    for (; idx < NN * NN; idx += stride) {
        int i = idx / NN, j = idx - i * NN;
        g_Sh[(size_t)i * KPAD + j] = __float2bfloat16(g_S[idx] * g_rrow[j]);
    }
}

// ---------------- pack x -> XtT bf16 (rows n=b*17+c, cols m) ----------------
__global__ void kPackT(const float* __restrict__ x) {
    int idx = blockIdx.x * blockDim.x + threadIdx.x;
    if (idx >= BC * NN) return;
    int n = idx / NN, m = idx - n * NN;
    int b = n / CC, c = n - b * CC;
    g_XtT[(size_t)n * KPAD + m] = __float2bfloat16(x[(size_t)(b * NN + m) * CC + c]);
}

// ---------------- bf16 tensor-core GEMM: C(2000,320) = S @ B ----------------
// phase 0: B^T = g_XtT -> Y1 fp32 + Y1T bf16 ; phase 1: B^T = g_Y1T -> Y2 fp32
__global__ __launch_bounds__(128) void kGemmMMA(int phase) {
    const __nv_bfloat16* __restrict__ Bt = phase ? g_Y1T : g_XtT;
    float* __restrict__ Y = phase ? g_Y2 : g_Y1;
    __shared__ __nv_bfloat16 As[64][72];
    __shared__ __nv_bfloat16 Bs[64][72];
    int m0 = blockIdx.x * 64, n0 = blockIdx.y * 64;
    int t = threadIdx.x;
    int wid = t >> 5, lane = t & 31;
    int wm = (wid >> 1) * 32, wn = (wid & 1) * 32;
    int grp = lane >> 2, tid4 = lane & 3;
    float acc[2][4][4] = {};

    for (int kc = 0; kc < KPAD / 64; kc++) {
        __syncthreads();
        // full 64x64 bf16 tile = 512 uint4 per matrix (4 iterations x 128 threads)
#pragma unroll
        for (int i = 0; i < 4; i++) {
            int idx = t + i * 128;           // [0, 512)
            int row = idx >> 3;              // [0, 64)
            int seg = idx & 7;               // [0, 8) -> seg*8 covers 64 bf16
            int gm = m0 + row; if (gm > NN - 1) gm = NN - 1;
            uint4 va = *(const uint4*)&g_Sh[(size_t)gm * KPAD + kc * 64 + seg * 8];
            *(uint4*)&As[row][seg * 8] = va;
            uint4 vb = *(const uint4*)&Bt[(size_t)(n0 + row) * KPAD + kc * 64 + seg * 8];
            *(uint4*)&Bs[row][seg * 8] = vb;
        }
        __syncthreads();
        const unsigned* Asu = (const unsigned*)As;   // row stride 36 u32
        const unsigned* Bsu = (const unsigned*)Bs;
#pragma unroll
        for (int ks = 0; ks < 4; ks++) {
            unsigned a[2][4], b[4][2];
            int cbase = ks * 8 + tid4;
#pragma unroll
            for (int mi = 0; mi < 2; mi++) {
                int r = wm + mi * 16 + grp;
                a[mi][0] = Asu[r * 36 + cbase];
                a[mi][1] = Asu[(r + 8) * 36 + cbase];
                a[mi][2] = Asu[r * 36 + cbase + 4];
                a[mi][3] = Asu[(r + 8) * 36 + cbase + 4];
            }
#pragma unroll
            for (int nj = 0; nj < 4; nj++) {
                int r = wn + nj * 8 + grp;
                b[nj][0] = Bsu[r * 36 + cbase];
                b[nj][1] = Bsu[r * 36 + cbase + 4];
            }
#pragma unroll
            for (int mi = 0; mi < 2; mi++)
#pragma unroll
                for (int nj = 0; nj < 4; nj++)
                    asm volatile(
                        "mma.sync.aligned.m16n8k16.row.col.f32.bf16.bf16.f32 "
                        "{%0,%1,%2,%3}, {%4,%5,%6,%7}, {%8,%9}, {%0,%1,%2,%3};"
                        : "+f"(acc[mi][nj][0]), "+f"(acc[mi][nj][1]),
                          "+f"(acc[mi][nj][2]), "+f"(acc[mi][nj][3])
                        : "r"(a[mi][0]), "r"(a[mi][1]), "r"(a[mi][2]), "r"(a[mi][3]),
                          "r"(b[nj][0]), "r"(b[nj][1]));
        }
    }
#pragma unroll
    for (int mi = 0; mi < 2; mi++) {
        int r0 = m0 + wm + mi * 16 + grp;
        int r1 = r0 + 8;
#pragma unroll
        for (int nj = 0; nj < 4; nj++) {
            int col = n0 + wn + nj * 8 + tid4 * 2;
            if (r0 < NN) {
                *(float2*)&Y[(size_t)r0 * NCP + col] = make_float2(acc[mi][nj][0], acc[mi][nj][1]);
                if (phase == 0) {
                    g_Y1T[(size_t)col * KPAD + r0]       = __float2bfloat16(acc[mi][nj][0]);
                    g_Y1T[(size_t)(col + 1) * KPAD + r0] = __float2bfloat16(acc[mi][nj][1]);
                }
            }
            if (r1 < NN) {
                *(float2*)&Y[(size_t)r1 * NCP + col] = make_float2(acc[mi][nj][2], acc[mi][nj][3]);
                if (phase == 0) {
                    g_Y1T[(size_t)col * KPAD + r1]       = __float2bfloat16(acc[mi][nj][2]);
                    g_Y1T[(size_t)(col + 1) * KPAD + r1] = __float2bfloat16(acc[mi][nj][3]);
                }
            }
        }
    }
}

// ---------------- adaptive weights: W[n,kc,o] = sum_d ne[n,d] wp[d,kc,o] ----------------
__global__ void kWeights(const float* __restrict__ ne, const float* __restrict__ wp) {
    __shared__ float nes[32][17];
    int j0 = blockIdx.x * 256;
    int n0 = blockIdx.y * 32;
    int t = threadIdx.x;
    for (int l = t; l < 32 * 16; l += 256) {
        int r = l >> 4, d = l & 15;
        nes[r][d] = (n0 + r < NN) ? ne[(n0 + r) * DD + d] : 0.f;
    }
    __syncthreads();
    int j = j0 + t;
    if (j < KCQ * O4) {
        float w[16];
#pragma unroll
        for (int d = 0; d < 16; d++) w[d] = wp[d * (KCQ * O4) + j];
        for (int r = 0; r < 32; r++) {
            int n = n0 + r;
            if (n >= NN) break;
            float acc = 0.f;
#pragma unroll
            for (int d = 0; d < 16; d++) acc += nes[r][d] * w[d];
            g_W[(size_t)n * (KCQ * O4) + j] = acc;
        }
    }
}

// ---------------- bias / wws / wwt ----------------
__global__ void kSmall(const float* __restrict__ ne, const float* __restrict__ bp,
                       const float* __restrict__ wwsp, const float* __restrict__ wwtp) {
    __shared__ float nn[16];
    int n = blockIdx.x, t = threadIdx.x;
    if (t < 16) nn[t] = ne[n * DD + t];
    __syncthreads();
    float acc = 0.f;
#pragma unroll
    for (int d = 0; d < 16; d++) acc += nn[d] * bp[d * OO + t];
    g_bias[n * OO + t] = acc;
    if (t < O8) {
        float a = 0.f;
#pragma unroll
        for (int d = 0; d < 16; d++) a += nn[d] * wwsp[d * O8 + t];
        g_wws[n * O8 + t] = a;
    }
    if (t < O2) {
        float a = 0.f;
#pragma unroll
        for (int d = 0; d < 16; d++) a += nn[d] * wwtp[d * O2 + t];
        g_wwt[n * O2 + t] = a;
    }
}

// ---------------- rsum[m] = sum_n gnn_w[m,n] ----------------
__global__ void kRsum(const float* __restrict__ gw) {
    __shared__ float red[128];
    int m = blockIdx.x, t = threadIdx.x;
    float s = 0.f;
    for (int j = t; j < NN; j += 128) s += gw[(size_t)m * NN + j];
    red[t] = s; __syncthreads();
    for (int st = 64; st > 0; st >>= 1) { if (t < st) red[t] += red[t + st]; __syncthreads(); }
    if (t == 0) g_rsum[m] = red[0];
}

// ---------------- temporal window reduce ----------------
__global__ void kXw(const float* __restrict__ xwin, const float* __restrict__ Tp) {
    int idx = blockIdx.x * blockDim.x + threadIdx.x;
    if (idx >= BB * NN) return;
    int b = idx / NN, n = idx % NN;
    float s = 0.f;
#pragma unroll
    for (int t = 0; t < WW; t++) s += xwin[(size_t)b * WW * NN + t * NN + n] * Tp[t];
    g_xw[idx] = s;
}

// ---------------- hodge branch: se/te ----------------
__global__ void kH1(const float* __restrict__ xew, const int* __restrict__ bidx,
                    const float* __restrict__ lw, const float* __restrict__ lb) {
    int idx = blockIdx.x * blockDim.x + threadIdx.x;
    if (idx >= BB * NE) return;
    int b = idx / NE, i = idx % NE;
    float w0 = lw[0], b0 = lb[0];
    float s = 0.f, tt = 0.f;
#pragma unroll
    for (int f = 0; f < NBB; f++) {
        int wv = bidx[f];
        float v = xew[(size_t)b * WW * NE + (size_t)wv * NE + i] * w0 + b0;
        s += v;
        tt += (float)(NBB - 1 - f) * v;
    }
    g_se[idx] = s;
    g_te[idx] = tt;
}

__global__ void kH2init(const int* __restrict__ jumpp) {
    int idx = blockIdx.x * blockDim.x + threadIdx.x;
    if (idx >= NE * BB) return;
    int e = idx / BB, b = idx % BB;
    g_mpT[idx] = decode_scalar(jumpp) * g_te[b * NE + e];
}

__global__ void kH2(const float* __restrict__ hodge) {
    __shared__ float ses[16][251];
    int j0 = blockIdx.x * 128;
    int i0 = blockIdx.y * 250;
    int t = threadIdx.x;
    for (int l = t; l < 16 * 250; l += 128) {
        int b = l / 250, ii = l % 250;
        ses[b][ii] = g_se[b * NE + i0 + ii];
    }
    __syncthreads();
    int j = j0 + t;
    if (j < NE) {
        float acc[16] = {};
        for (int ii = 0; ii < 250; ii++) {
            float h = hodge[(size_t)(i0 + ii) * NE + j];
#pragma unroll
            for (int b = 0; b < 16; b++) acc[b] += ses[b][ii] * h;
        }
#pragma unroll
        for (int b = 0; b < 16; b++) atomicAdd(&g_mpT[j * BB + b], acc[b]);
    }
}

// xm[n,b] = (1/nb) sum_e mpT[e,b] * inc[n,e]
__global__ void kH3(const float* __restrict__ inc, int nb) {
    __shared__ float incs[16][65];
    __shared__ float mps[64][17];
    int n0 = blockIdx.x * 16;
    int t = threadIdx.x;
    int nr = t >> 4, b = t & 15;
    float acc = 0.f;
    for (int e0 = 0; e0 < NE; e0 += 64) {
        for (int l = t; l < 1024; l += 256) {
            int r = l >> 6, ee = l & 63;
            int e = e0 + ee;
            incs[r][ee] = (e < NE) ? inc[(size_t)(n0 + r) * NE + e] : 0.f;
        }
        for (int l = t; l < 1024; l += 256) {
            int ee = l >> 4, bb = l & 15;
            int e = e0 + ee;
            mps[ee][bb] = (e < NE) ? g_mpT[e * BB + bb] : 0.f;
        }
        __syncthreads();
#pragma unroll 8
        for (int ee = 0; ee < 64; ee++) acc += incs[nr][ee] * mps[ee][b];
        __syncthreads();
    }
    g_xm[(n0 + nr) * BB + b] = acc / (float)nb;
}

// ---------------- diffusion epilogue: out[:, :, 0:64] ----------------
__global__ __launch_bounds__(256) void kF1(const float* __restrict__ x, float* __restrict__ out) {
    __shared__ float ws[KCQ * O4];
    __shared__ float xs[BB][KCQ + 1];
    int n = blockIdx.x, t = threadIdx.x;
    for (int l = t; l < KCQ * O4; l += 256) ws[l] = g_W[(size_t)n * (KCQ * O4) + l];
    for (int l = t; l < BB * KCQ; l += 256) {
        int b = l / KCQ, kc = l % KCQ;
        int k = kc / CC, c = kc % CC;
        float v;
        if (k == 0)      v = x[(size_t)(b * NN + n) * CC + c];
        else if (k == 1) v = g_Y1[(size_t)n * NCP + b * CC + c];
        else             v = g_Y2[(size_t)n * NCP + b * CC + c];
        xs[b][kc] = v;
    }
    __syncthreads();
    int o = t & 63, bq = t >> 6;
    int b0 = bq * 4;
    float a0 = 0.f, a1 = 0.f, a2 = 0.f, a3 = 0.f;
    for (int kc = 0; kc < KCQ; kc++) {
        float w = ws[kc * O4 + o];
        a0 += xs[b0 + 0][kc] * w;
        a1 += xs[b0 + 1][kc] * w;
        a2 += xs[b0 + 2][kc] * w;
        a3 += xs[b0 + 3][kc] * w;
    }
    float bi = g_bias[n * OO + o];
    out[(size_t)((b0 + 0) * NN + n) * OO + o] = a0 + bi;
    out[(size_t)((b0 + 1) * NN + n) * OO + o] = a1 + bi;
    out[(size_t)((b0 + 2) * NN + n) * OO + o] = a2 + bi;
    out[(size_t)((b0 + 3) * NN + n) * OO + o] = a3 + bi;
}

// ---------------- ZFC + temporal + supra epilogues: out[:, :, 64:256] ----------------
__global__ void kFrest(const float* __restrict__ zin, const float* __restrict__ gnnb,
                       float* __restrict__ out) {
    int bx = blockIdx.x;
    int n = bx % NN, b = bx / NN;
    int j = threadIdx.x;   // 0..191
    float v; int o;
    if (j < 32) {
        int k = n * 32 + j;
        int q = k / NN;
        int m = k - q * NN;
        v = fmaxf(zin[b * 32 + q] * g_rsum[m] + gnnb[m], 0.f);
        o = 64 + j;
    } else if (j < 160) {
        int jj = j - 32;
        v = g_xw[b * NN + n] * g_wwt[n * O2 + jj];
        o = 96 + jj;
    } else {
        int jj = j - 160;
        v = g_xm[n * BB + b] * g_wws[n * O8 + jj];
        o = 224 + jj;
    }
    out[(size_t)(b * NN + n) * OO + o] = v + g_bias[n * OO + o];
}

// ---------------- launch ----------------
extern "C" void kernel_launch(void* const* d_in, const int* in_sizes, int n_in,
                              void* d_out, int out_size) {
    const float* x     = (const float*)d_in[0];
    const float* xwin  = (const float*)d_in[1];
    const float* ne    = (const float*)d_in[2];
    const int*   fixed = (const int*)  d_in[3];
    const float* adj   = (const float*)d_in[4];
    const int*   stay  = (const int*)  d_in[5];
    const int*   jump  = (const int*)  d_in[6];
    const float* zin   = (const float*)d_in[7];
    const float* hodge = (const float*)d_in[8];
    const float* xew   = (const float*)d_in[9];
    const float* inc   = (const float*)d_in[10];
    const float* wp    = (const float*)d_in[11];
    const float* wwsp  = (const float*)d_in[12];
    const float* wwtp  = (const float*)d_in[13];
    const float* bp    = (const float*)d_in[14];
    const float* Tp    = (const float*)d_in[15];
    const float* lw    = (const float*)d_in[16];
    const float* lb    = (const float*)d_in[17];
    const float* gw    = (const float*)d_in[18];
    const float* gnnb  = (const float*)d_in[19];
    const int*   bidx  = (const int*)  d_in[20];
    float* out = (float*)d_out;
    int nb = in_sizes[20];   // NB = 3

    // adjacency / transition matrix -> bf16 S
    kS0<<<dim3(63, 63), 256>>>(ne, stay);
    kSoftmax<<<NN, 256>>>(adj, fixed);
    kRowsumS<<<NN, 256>>>(fixed);     // fixed-adj path only (early exit)
    kColDivH<<<512, 256>>>(fixed);    // fixed-adj path only (early exit)

    // diffusion GEMMs on tensor cores (bf16 in, fp32 acc)
    kPackT<<<(BC * NN + 255) / 256, 256>>>(x);
    kGemmMMA<<<dim3(32, 5), 128>>>(0);
    kGemmMMA<<<dim3(32, 5), 128>>>(1);

    // adaptive params
    kWeights<<<dim3(13, 63), 256>>>(ne, wp);
    kSmall<<<NN, 256>>>(ne, bp, wwsp, wwtp);

    // ZFC / temporal
    kRsum<<<NN, 128>>>(gw);
    kXw<<<(BB * NN + 255) / 256, 256>>>(xwin, Tp);

    // hodge / supra branch
    kH1<<<(BB * NE + 255) / 256, 256>>>(xew, bidx, lw, lb);
    kH2init<<<(NE * BB + 255) / 256, 256>>>(jump);
    kH2<<<dim3(24, 12), 128>>>(hodge);
    kH3<<<125, 256>>>(inc, nb);

    // output assembly
    kF1<<<NN, 256>>>(x, out);
    kFrest<<<BB * NN, 192>>>(zin, gnnb, out);
}

// round 5
// speedup vs baseline: 1.6580x; 1.1918x over previous
#include <cuda_runtime.h>
#include <cuda_bf16.h>
#include <math.h>

// Problem dims
#define NN   2000
#define NE   3000
#define BB   16
#define CC   17
#define WW   12
#define DD   16
#define OO   256
#define KK   3
#define NBB  3
#define BC   (BB*CC)    // 272
#define NCP  320        // fp32 Y stride
#define KPAD 2048       // bf16 padded k-stride (zero-init padding is load-bearing)
#define KCQ  (KK*CC)    // 51
#define O4   64
#define O8   32
#define O2   128

// ---------------- scratch (device globals; no runtime alloc) ----------------
__device__ float g_S[NN*NN];                 // fixed-adj path only
__device__ __nv_bfloat16 g_Sh[NN*KPAD];      // bf16 S (pad cols zero)
__device__ __nv_bfloat16 g_XtT[NCP*KPAD];    // bf16 X^T rows n=b*17+c, cols m
__device__ __nv_bfloat16 g_Y1T[NCP*KPAD];    // bf16 Y1^T
__device__ float g_rrow[NN];
__device__ float g_Y1[NN*NCP];
__device__ float g_Y2[NN*NCP];
__device__ __nv_bfloat16 g_Wh[NN*KCQ*O4];    // adaptive weights (bf16, 13 MB)
__device__ float g_bias[NN*OO];
__device__ float g_wws[NN*O8];
__device__ float g_wwt[NN*O2];
__device__ float g_xw[BB*NN];
__device__ float g_se[BB*NE];
__device__ float g_mpT[NE*BB];
__device__ float g_xm[NN*BB];
__device__ float g_rsum[NN];

__device__ __forceinline__ float decode_scalar(const int* p) {
    int iv = *p;
    return (iv > -1000000 && iv < 1000000) ? (float)iv : __int_as_float(iv);
}

// ---------------- fused: S0 = relu(ne@ne^T) diag=stay, softmax -> bf16 S ----------------
// 4 rows per block, row values live in registers; ne streamed from L2.
__global__ __launch_bounds__(256) void kS0Softmax(const float* __restrict__ ne,
                                                  const float* __restrict__ adj,
                                                  const int* __restrict__ stay,
                                                  const int* __restrict__ fixedp) {
    __shared__ float4 red4[256];
    int i0 = blockIdx.x * 4;
    int t = threadIdx.x;
    bool isfixed = (decode_scalar(fixedp) != 0.0f);
    float sc = decode_scalar(stay);

    float nei[4][16];
#pragma unroll
    for (int r = 0; r < 4; r++)
#pragma unroll
        for (int q = 0; q < 4; q++) {
            float4 v = __ldg((const float4*)&ne[(size_t)(i0 + r) * DD + q * 4]);
            nei[r][q * 4 + 0] = v.x; nei[r][q * 4 + 1] = v.y;
            nei[r][q * 4 + 2] = v.z; nei[r][q * 4 + 3] = v.w;
        }

    float vals[4][8];
    float4 mx = make_float4(-1e30f, -1e30f, -1e30f, -1e30f);
#pragma unroll
    for (int jj = 0; jj < 8; jj++) {
        int j = t + jj * 256;
        if (j < NN) {
            float nej[16];
#pragma unroll
            for (int q = 0; q < 4; q++) {
                float4 v = __ldg((const float4*)&ne[(size_t)j * DD + q * 4]);
                nej[q * 4 + 0] = v.x; nej[q * 4 + 1] = v.y;
                nej[q * 4 + 2] = v.z; nej[q * 4 + 3] = v.w;
            }
#pragma unroll
            for (int r = 0; r < 4; r++) {
                float acc = 0.f;
#pragma unroll
                for (int d = 0; d < 16; d++) acc += nei[r][d] * nej[d];
                float v = (j == i0 + r) ? sc : fmaxf(acc, 0.f);
                vals[r][jj] = v;
            }
            mx.x = fmaxf(mx.x, vals[0][jj]); mx.y = fmaxf(mx.y, vals[1][jj]);
            mx.z = fmaxf(mx.z, vals[2][jj]); mx.w = fmaxf(mx.w, vals[3][jj]);
        } else {
#pragma unroll
            for (int r = 0; r < 4; r++) vals[r][jj] = -1e30f;
        }
    }
    // block max reduce (softmax path only needs it, cheap anyway)
    red4[t] = mx; __syncthreads();
    for (int s = 128; s > 0; s >>= 1) {
        if (t < s) {
            float4 o = red4[t + s];
            red4[t].x = fmaxf(red4[t].x, o.x); red4[t].y = fmaxf(red4[t].y, o.y);
            red4[t].z = fmaxf(red4[t].z, o.z); red4[t].w = fmaxf(red4[t].w, o.w);
        }
        __syncthreads();
    }
    mx = red4[0]; __syncthreads();
    float mxa[4] = {mx.x, mx.y, mx.z, mx.w};

    float4 sum = make_float4(0.f, 0.f, 0.f, 0.f);
    float suma[4] = {0.f, 0.f, 0.f, 0.f};
#pragma unroll
    for (int jj = 0; jj < 8; jj++) {
        int j = t + jj * 256;
        if (j < NN) {
#pragma unroll
            for (int r = 0; r < 4; r++) {
                float e;
                if (!isfixed) e = expf(vals[r][jj] - mxa[r]);
                else          e = __ldg(&adj[(size_t)(i0 + r) * NN + j]) * expf(vals[r][jj]);
                vals[r][jj] = e;
                suma[r] += e;
            }
        }
    }
    sum = make_float4(suma[0], suma[1], suma[2], suma[3]);
    red4[t] = sum; __syncthreads();
    for (int s = 128; s > 0; s >>= 1) {
        if (t < s) {
            float4 o = red4[t + s];
            red4[t].x += o.x; red4[t].y += o.y; red4[t].z += o.z; red4[t].w += o.w;
        }
        __syncthreads();
    }
    sum = red4[0];
    float inv[4] = {1.f / sum.x, 1.f / sum.y, 1.f / sum.z, 1.f / sum.w};

    if (!isfixed) {
        // post-softmax rowsum==1 to ~6e-7; column division is identity at our budget
#pragma unroll
        for (int jj = 0; jj < 8; jj++) {
            int j = t + jj * 256;
            if (j < NN)
#pragma unroll
                for (int r = 0; r < 4; r++)
                    g_Sh[(size_t)(i0 + r) * KPAD + j] = __float2bfloat16(vals[r][jj] * inv[r]);
        }
    } else {
#pragma unroll
        for (int jj = 0; jj < 8; jj++) {
            int j = t + jj * 256;
            if (j < NN)
#pragma unroll
                for (int r = 0; r < 4; r++)
                    g_S[(size_t)(i0 + r) * NN + j] = vals[r][jj];
        }
        if (t < 4) g_rrow[i0 + t] = inv[t];
    }
}

// fixed-adj path only: column j scaled by 1/rowsum[j], emit bf16
__global__ void kColDivH(const int* __restrict__ fixedp) {
    if (decode_scalar(fixedp) == 0.0f) return;
    int idx = blockIdx.x * blockDim.x + threadIdx.x;
    int stride = gridDim.x * blockDim.x;
    for (; idx < NN * NN; idx += stride) {
        int i = idx / NN, j = idx - i * NN;
        g_Sh[(size_t)i * KPAD + j] = __float2bfloat16(g_S[idx] * g_rrow[j]);
    }
}

// ---------------- prep: bias/wws/wwt + gnn rowsum + temporal + packT ----------------
__global__ __launch_bounds__(256) void kPrep(const float* __restrict__ ne,
                                             const float* __restrict__ bp,
                                             const float* __restrict__ wwsp,
                                             const float* __restrict__ wwtp,
                                             const float* __restrict__ gw,
                                             const float* __restrict__ xwin,
                                             const float* __restrict__ Tp,
                                             const float* __restrict__ x) {
    __shared__ float nn[16];
    __shared__ float red[256];
    int n = blockIdx.x, t = threadIdx.x;
    if (t < 16) nn[t] = ne[n * DD + t];
    __syncthreads();
    // bias (O=256)
    {
        float acc = 0.f;
#pragma unroll
        for (int d = 0; d < 16; d++) acc += nn[d] * bp[d * OO + t];
        g_bias[n * OO + t] = acc;
    }
    if (t < O8) {
        float a = 0.f;
#pragma unroll
        for (int d = 0; d < 16; d++) a += nn[d] * wwsp[d * O8 + t];
        g_wws[n * O8 + t] = a;
    }
    if (t < O2) {
        float a = 0.f;
#pragma unroll
        for (int d = 0; d < 16; d++) a += nn[d] * wwtp[d * O2 + t];
        g_wwt[n * O2 + t] = a;
    }
    // gnn_w rowsum
    {
        float s = 0.f;
        for (int j = t; j < NN; j += 256) s += gw[(size_t)n * NN + j];
        red[t] = s; __syncthreads();
        for (int st = 128; st > 0; st >>= 1) { if (t < st) red[t] += red[t + st]; __syncthreads(); }
        if (t == 0) g_rsum[n] = red[0];
    }
    // temporal window reduce for node n (one thread per batch)
    if (t < BB) {
        float s = 0.f;
#pragma unroll
        for (int w = 0; w < WW; w++) s += xwin[(size_t)t * WW * NN + (size_t)w * NN + n] * Tp[w];
        g_xw[t * NN + n] = s;
    }
    // pack x column for node n (bf16 X^T)
    for (int l = t; l < BC; l += 256) {
        int b = l / CC, c = l - b * CC;
        g_XtT[(size_t)l * KPAD + n] = __float2bfloat16(x[(size_t)(b * NN + n) * CC + c]);
    }
}

// ---------------- bf16 MMA GEMM, double-buffered: C(2000,320) = S @ B ----------------
__global__ __launch_bounds__(256) void kGemmMMA(int phase) {
    const __nv_bfloat16* __restrict__ Bt = phase ? g_Y1T : g_XtT;
    float* __restrict__ Y = phase ? g_Y2 : g_Y1;
    __shared__ __nv_bfloat16 As[2][64][72];
    __shared__ __nv_bfloat16 Bs[2][64][72];
    int m0 = blockIdx.x * 64, n0 = blockIdx.y * 64;
    int t = threadIdx.x;
    int wid = t >> 5, lane = t & 31;
    int wm = (wid & 3) * 16, wn = (wid >> 2) * 32;
    int grp = lane >> 2, tid4 = lane & 3;
    float acc[4][4] = {};

    int row0 = t >> 3, seg = t & 7;        // chunk 0: rows 0..31
    int row1 = row0 + 32;                  // chunk 1: rows 32..63
    int gmA0 = m0 + row0; if (gmA0 > NN - 1) gmA0 = NN - 1;
    int gmA1 = m0 + row1; if (gmA1 > NN - 1) gmA1 = NN - 1;
    const __nv_bfloat16* a0p = &g_Sh[(size_t)gmA0 * KPAD + seg * 8];
    const __nv_bfloat16* a1p = &g_Sh[(size_t)gmA1 * KPAD + seg * 8];
    const __nv_bfloat16* b0p = &Bt[(size_t)(n0 + row0) * KPAD + seg * 8];
    const __nv_bfloat16* b1p = &Bt[(size_t)(n0 + row1) * KPAD + seg * 8];

    // preload kc=0
    uint4 av0 = *(const uint4*)(a0p);
    uint4 av1 = *(const uint4*)(a1p);
    uint4 bv0 = *(const uint4*)(b0p);
    uint4 bv1 = *(const uint4*)(b1p);
    *(uint4*)&As[0][row0][seg * 8] = av0;
    *(uint4*)&As[0][row1][seg * 8] = av1;
    *(uint4*)&Bs[0][row0][seg * 8] = bv0;
    *(uint4*)&Bs[0][row1][seg * 8] = bv1;
    __syncthreads();

    for (int kc = 0; kc < KPAD / 64; kc++) {
        int cur = kc & 1;
        if (kc + 1 < KPAD / 64) {
            size_t off = (size_t)(kc + 1) * 64;
            av0 = *(const uint4*)(a0p + off);
            av1 = *(const uint4*)(a1p + off);
            bv0 = *(const uint4*)(b0p + off);
            bv1 = *(const uint4*)(b1p + off);
        }
        const unsigned* Asu = (const unsigned*)As[cur];   // row stride 36 u32
        const unsigned* Bsu = (const unsigned*)Bs[cur];
#pragma unroll
        for (int ks = 0; ks < 4; ks++) {
            int cbase = ks * 8 + tid4;
            int ra = wm + grp;
            unsigned a0 = Asu[ra * 36 + cbase];
            unsigned a1 = Asu[(ra + 8) * 36 + cbase];
            unsigned a2 = Asu[ra * 36 + cbase + 4];
            unsigned a3 = Asu[(ra + 8) * 36 + cbase + 4];
#pragma unroll
            for (int nj = 0; nj < 4; nj++) {
                int rb = wn + nj * 8 + grp;
                unsigned b0 = Bsu[rb * 36 + cbase];
                unsigned b1 = Bsu[rb * 36 + cbase + 4];
                asm volatile(
                    "mma.sync.aligned.m16n8k16.row.col.f32.bf16.bf16.f32 "
                    "{%0,%1,%2,%3}, {%4,%5,%6,%7}, {%8,%9}, {%0,%1,%2,%3};"
                    : "+f"(acc[nj][0]), "+f"(acc[nj][1]),
                      "+f"(acc[nj][2]), "+f"(acc[nj][3])
                    : "r"(a0), "r"(a1), "r"(a2), "r"(a3), "r"(b0), "r"(b1));
            }
        }
        if (kc + 1 < KPAD / 64) {
            int nxt = cur ^ 1;
            *(uint4*)&As[nxt][row0][seg * 8] = av0;
            *(uint4*)&As[nxt][row1][seg * 8] = av1;
            *(uint4*)&Bs[nxt][row0][seg * 8] = bv0;
            *(uint4*)&Bs[nxt][row1][seg * 8] = bv1;
        }
        __syncthreads();
    }

    int r0 = m0 + wm + grp, r1 = r0 + 8;
#pragma unroll
    for (int nj = 0; nj < 4; nj++) {
        int col = n0 + wn + nj * 8 + tid4 * 2;
        if (r0 < NN) {
            *(float2*)&Y[(size_t)r0 * NCP + col] = make_float2(acc[nj][0], acc[nj][1]);
            if (phase == 0) {
                g_Y1T[(size_t)col * KPAD + r0]       = __float2bfloat16(acc[nj][0]);
                g_Y1T[(size_t)(col + 1) * KPAD + r0] = __float2bfloat16(acc[nj][1]);
            }
        }
        if (r1 < NN) {
            *(float2*)&Y[(size_t)r1 * NCP + col] = make_float2(acc[nj][2], acc[nj][3]);
            if (phase == 0) {
                g_Y1T[(size_t)col * KPAD + r1]       = __float2bfloat16(acc[nj][2]);
                g_Y1T[(size_t)(col + 1) * KPAD + r1] = __float2bfloat16(acc[nj][3]);
            }
        }
    }
}

// ---------------- adaptive weights (bf16 out): W[n,kc,o] = sum_d ne[n,d] wp[d,kc,o] ----------------
__global__ void kWeights(const float* __restrict__ ne, const float* __restrict__ wp) {
    __shared__ float nes[32][17];
    int j0 = blockIdx.x * 256;
    int n0 = blockIdx.y * 32;
    int t = threadIdx.x;
    for (int l = t; l < 32 * 16; l += 256) {
        int r = l >> 4, d = l & 15;
        nes[r][d] = (n0 + r < NN) ? ne[(n0 + r) * DD + d] : 0.f;
    }
    __syncthreads();
    int j = j0 + t;
    if (j < KCQ * O4) {
        float w[16];
#pragma unroll
        for (int d = 0; d < 16; d++) w[d] = wp[d * (KCQ * O4) + j];
        for (int r = 0; r < 32; r++) {
            int n = n0 + r;
            if (n >= NN) break;
            float acc = 0.f;
#pragma unroll
            for (int d = 0; d < 16; d++) acc += nes[r][d] * w[d];
            g_Wh[(size_t)n * (KCQ * O4) + j] = __float2bfloat16(acc);
        }
    }
}

// ---------------- hodge: se + mpT init (jump*te) ----------------
__global__ void kH1(const float* __restrict__ xew, const int* __restrict__ bidx,
                    const float* __restrict__ lw, const float* __restrict__ lb,
                    const int* __restrict__ jumpp) {
    int idx = blockIdx.x * blockDim.x + threadIdx.x;
    if (idx >= BB * NE) return;
    int b = idx / NE, i = idx % NE;
    float w0 = lw[0], b0 = lb[0];
    float jc = decode_scalar(jumpp);
    float s = 0.f, tt = 0.f;
#pragma unroll
    for (int f = 0; f < NBB; f++) {
        int wv = bidx[f];
        float v = xew[(size_t)b * WW * NE + (size_t)wv * NE + i] * w0 + b0;
        s += v;
        tt += (float)(NBB - 1 - f) * v;
    }
    g_se[idx] = s;
    g_mpT[i * BB + b] = jc * tt;
}

__global__ void kH2(const float* __restrict__ hodge) {
    __shared__ float ses[16][251];
    int j0 = blockIdx.x * 128;
    int i0 = blockIdx.y * 250;
    int t = threadIdx.x;
    for (int l = t; l < 16 * 250; l += 128) {
        int b = l / 250, ii = l % 250;
        ses[b][ii] = g_se[b * NE + i0 + ii];
    }
    __syncthreads();
    int j = j0 + t;
    if (j < NE) {
        float acc[16] = {};
        for (int ii = 0; ii < 250; ii++) {
            float h = hodge[(size_t)(i0 + ii) * NE + j];
#pragma unroll
            for (int b = 0; b < 16; b++) acc[b] += ses[b][ii] * h;
        }
#pragma unroll
        for (int b = 0; b < 16; b++) atomicAdd(&g_mpT[j * BB + b], acc[b]);
    }
}

// xm[n,b] = (1/nb) sum_e mpT[e,b] * inc[n,e]
__global__ void kH3(const float* __restrict__ inc, int nb) {
    __shared__ float incs[16][65];
    __shared__ float mps[64][17];
    int n0 = blockIdx.x * 16;
    int t = threadIdx.x;
    int nr = t >> 4, b = t & 15;
    float acc = 0.f;
    for (int e0 = 0; e0 < NE; e0 += 64) {
        for (int l = t; l < 1024; l += 256) {
            int r = l >> 6, ee = l & 63;
            int e = e0 + ee;
            incs[r][ee] = (e < NE) ? inc[(size_t)(n0 + r) * NE + e] : 0.f;
        }
        for (int l = t; l < 1024; l += 256) {
            int ee = l >> 4, bb = l & 15;
            int e = e0 + ee;
            mps[ee][bb] = (e < NE) ? g_mpT[e * BB + bb] : 0.f;
        }
        __syncthreads();
#pragma unroll 8
        for (int ee = 0; ee < 64; ee++) acc += incs[nr][ee] * mps[ee][b];
        __syncthreads();
    }
    g_xm[(n0 + nr) * BB + b] = acc / (float)nb;
}

// ---------------- diffusion epilogue: out[:, :, 0:64] ----------------
__global__ __launch_bounds__(256) void kF1(const float* __restrict__ x, float* __restrict__ out) {
    __shared__ float ws[KCQ * O4];
    __shared__ float xs[BB][KCQ + 1];
    int n = blockIdx.x, t = threadIdx.x;
    for (int l = t; l < KCQ * O4; l += 256)
        ws[l] = __bfloat162float(g_Wh[(size_t)n * (KCQ * O4) + l]);
    for (int l = t; l < BB * KCQ; l += 256) {
        int b = l / KCQ, kc = l % KCQ;
        int k = kc / CC, c = kc % CC;
        float v;
        if (k == 0)      v = x[(size_t)(b * NN + n) * CC + c];
        else if (k == 1) v = g_Y1[(size_t)n * NCP + b * CC + c];
        else             v = g_Y2[(size_t)n * NCP + b * CC + c];
        xs[b][kc] = v;
    }
    __syncthreads();
    int o = t & 63, bq = t >> 6;
    int b0 = bq * 4;
    float a0 = 0.f, a1 = 0.f, a2 = 0.f, a3 = 0.f;
    for (int kc = 0; kc < KCQ; kc++) {
        float w = ws[kc * O4 + o];
        a0 += xs[b0 + 0][kc] * w;
        a1 += xs[b0 + 1][kc] * w;
        a2 += xs[b0 + 2][kc] * w;
        a3 += xs[b0 + 3][kc] * w;
    }
    float bi = g_bias[n * OO + o];
    out[(size_t)((b0 + 0) * NN + n) * OO + o] = a0 + bi;
    out[(size_t)((b0 + 1) * NN + n) * OO + o] = a1 + bi;
    out[(size_t)((b0 + 2) * NN + n) * OO + o] = a2 + bi;
    out[(size_t)((b0 + 3) * NN + n) * OO + o] = a3 + bi;
}

// ---------------- ZFC + temporal + supra epilogues: out[:, :, 64:256] ----------------
// one block per node, loop over batch
__global__ __launch_bounds__(192) void kFrest(const float* __restrict__ zin,
                                              const float* __restrict__ gnnb,
                                              float* __restrict__ out) {
    int n = blockIdx.x;
    int j = threadIdx.x;   // 0..191
    int o;
    float bi;
    // per-thread batch-invariant setup
    int q = 0, m = 0; float zr = 0.f, gb = 0.f, wwtv = 0.f, wwsv = 0.f;
    if (j < 32) {
        int k = n * 32 + j;
        q = k / NN; m = k - q * NN;
        zr = g_rsum[m]; gb = gnnb[m];
        o = 64 + j;
    } else if (j < 160) {
        wwtv = g_wwt[n * O2 + (j - 32)];
        o = 96 + (j - 32);
    } else {
        wwsv = g_wws[n * O8 + (j - 160)];
        o = 224 + (j - 160);
    }
    bi = g_bias[n * OO + o];
#pragma unroll
    for (int b = 0; b < BB; b++) {
        float v;
        if (j < 32)       v = fmaxf(zin[b * 32 + q] * zr + gb, 0.f);
        else if (j < 160) v = g_xw[b * NN + n] * wwtv;
        else              v = g_xm[n * BB + b] * wwsv;
        out[(size_t)(b * NN + n) * OO + o] = v + bi;
    }
}

// ---------------- launch ----------------
extern "C" void kernel_launch(void* const* d_in, const int* in_sizes, int n_in,
                              void* d_out, int out_size) {
    const float* x     = (const float*)d_in[0];
    const float* xwin  = (const float*)d_in[1];
    const float* ne    = (const float*)d_in[2];
    const int*   fixed = (const int*)  d_in[3];
    const float* adj   = (const float*)d_in[4];
    const int*   stay  = (const int*)  d_in[5];
    const int*   jump  = (const int*)  d_in[6];
    const float* zin   = (const float*)d_in[7];
    const float* hodge = (const float*)d_in[8];
    const float* xew   = (const float*)d_in[9];
    const float* inc   = (const float*)d_in[10];
    const float* wp    = (const float*)d_in[11];
    const float* wwsp  = (const float*)d_in[12];
    const float* wwtp  = (const float*)d_in[13];
    const float* bp    = (const float*)d_in[14];
    const float* Tp    = (const float*)d_in[15];
    const float* lw    = (const float*)d_in[16];
    const float* lb    = (const float*)d_in[17];
    const float* gw    = (const float*)d_in[18];
    const float* gnnb  = (const float*)d_in[19];
    const int*   bidx  = (const int*)  d_in[20];
    float* out = (float*)d_out;
    int nb = in_sizes[20];   // NB = 3

    // transition matrix -> bf16 S (fused)
    kS0Softmax<<<500, 256>>>(ne, adj, stay, fixed);
    kColDivH<<<512, 256>>>(fixed);           // dead on softmax path

    // prep: bias/wws/wwt + rsum + xw + packT
    kPrep<<<NN, 256>>>(ne, bp, wwsp, wwtp, gw, xwin, Tp, x);

    // diffusion GEMMs (tensor cores, double-buffered)
    kGemmMMA<<<dim3(32, 5), 256>>>(0);
    kGemmMMA<<<dim3(32, 5), 256>>>(1);

    // adaptive weights (bf16)
    kWeights<<<dim3(13, 63), 256>>>(ne, wp);

    // hodge / supra branch
    kH1<<<(BB * NE + 255) / 256, 256>>>(xew, bidx, lw, lb, jump);
    kH2<<<dim3(24, 12), 128>>>(hodge);
    kH3<<<125, 256>>>(inc, nb);

    // output assembly
    kF1<<<NN, 256>>>(x, out);
    kFrest<<<NN, 192>>>(zin, gnnb, out);
}

// round 6
// speedup vs baseline: 1.6990x; 1.0247x over previous
#include <cuda_runtime.h>
#include <cuda_fp16.h>
#include <math.h>

// Problem dims
#define NN   2000
#define NE   3000
#define BB   16
#define CC   17
#define WW   12
#define DD   16
#define OO   256
#define KK   3
#define NBB  3
#define BC   (BB*CC)    // 272
#define NCP  320        // fp32 Y stride
#define KPAD 2048       // fp16 padded k-stride (zero-init padding is load-bearing)
#define KCQ  (KK*CC)    // 51
#define O4   64
#define O8   32
#define O2   128

// ---------------- scratch (device globals; no runtime alloc) ----------------
__device__ float g_S[NN*NN];                 // fixed-adj path only
__device__ __half g_Sh[NN*KPAD];             // fp16 S (pad cols zero)
__device__ __half g_XtT[NCP*KPAD];           // fp16 X^T rows n=b*17+c, cols m
__device__ __half g_Y1T[NCP*KPAD];           // fp16 Y1^T
__device__ float g_rrow[NN];
__device__ float g_Y1[NN*NCP];
__device__ float g_Y2[NN*NCP];
__device__ __half g_Wh[NN*KCQ*O4];           // adaptive weights (fp16, 13 MB)
__device__ float g_bias[NN*OO];
__device__ float g_wws[NN*O8];
__device__ float g_wwt[NN*O2];
__device__ float g_xw[BB*NN];
__device__ float g_se[BB*NE];
__device__ float g_mpT[NE*BB];
__device__ float g_xm[NN*BB];
__device__ float g_rsum[NN];

__device__ __forceinline__ float decode_scalar(const int* p) {
    int iv = *p;
    return (iv > -1000000 && iv < 1000000) ? (float)iv : __int_as_float(iv);
}

__device__ __forceinline__ unsigned cvta_s(const void* p) {
    return (unsigned)__cvta_generic_to_shared(p);
}

// ---------------- fused: S0 = relu(ne@ne^T) diag=stay, softmax -> fp16 S ----------------
__global__ __launch_bounds__(256) void kS0Softmax(const float* __restrict__ ne,
                                                  const float* __restrict__ adj,
                                                  const int* __restrict__ stay,
                                                  const int* __restrict__ fixedp) {
    __shared__ float4 red4[256];
    int i0 = blockIdx.x * 4;
    int t = threadIdx.x;
    bool isfixed = (decode_scalar(fixedp) != 0.0f);
    float sc = decode_scalar(stay);

    float nei[4][16];
#pragma unroll
    for (int r = 0; r < 4; r++)
#pragma unroll
        for (int q = 0; q < 4; q++) {
            float4 v = __ldg((const float4*)&ne[(size_t)(i0 + r) * DD + q * 4]);
            nei[r][q * 4 + 0] = v.x; nei[r][q * 4 + 1] = v.y;
            nei[r][q * 4 + 2] = v.z; nei[r][q * 4 + 3] = v.w;
        }

    float vals[4][8];
    float4 mx = make_float4(-1e30f, -1e30f, -1e30f, -1e30f);
#pragma unroll
    for (int jj = 0; jj < 8; jj++) {
        int j = t + jj * 256;
        if (j < NN) {
            float nej[16];
#pragma unroll
            for (int q = 0; q < 4; q++) {
                float4 v = __ldg((const float4*)&ne[(size_t)j * DD + q * 4]);
                nej[q * 4 + 0] = v.x; nej[q * 4 + 1] = v.y;
                nej[q * 4 + 2] = v.z; nej[q * 4 + 3] = v.w;
            }
#pragma unroll
            for (int r = 0; r < 4; r++) {
                float acc = 0.f;
#pragma unroll
                for (int d = 0; d < 16; d++) acc += nei[r][d] * nej[d];
                vals[r][jj] = (j == i0 + r) ? sc : fmaxf(acc, 0.f);
            }
            mx.x = fmaxf(mx.x, vals[0][jj]); mx.y = fmaxf(mx.y, vals[1][jj]);
            mx.z = fmaxf(mx.z, vals[2][jj]); mx.w = fmaxf(mx.w, vals[3][jj]);
        } else {
#pragma unroll
            for (int r = 0; r < 4; r++) vals[r][jj] = -1e30f;
        }
    }
    red4[t] = mx; __syncthreads();
    for (int s = 128; s > 0; s >>= 1) {
        if (t < s) {
            float4 o = red4[t + s];
            red4[t].x = fmaxf(red4[t].x, o.x); red4[t].y = fmaxf(red4[t].y, o.y);
            red4[t].z = fmaxf(red4[t].z, o.z); red4[t].w = fmaxf(red4[t].w, o.w);
        }
        __syncthreads();
    }
    mx = red4[0]; __syncthreads();
    float mxa[4] = {mx.x, mx.y, mx.z, mx.w};

    float suma[4] = {0.f, 0.f, 0.f, 0.f};
#pragma unroll
    for (int jj = 0; jj < 8; jj++) {
        int j = t + jj * 256;
        if (j < NN) {
#pragma unroll
            for (int r = 0; r < 4; r++) {
                float e;
                if (!isfixed) e = expf(vals[r][jj] - mxa[r]);
                else          e = __ldg(&adj[(size_t)(i0 + r) * NN + j]) * expf(vals[r][jj]);
                vals[r][jj] = e;
                suma[r] += e;
            }
        }
    }
    red4[t] = make_float4(suma[0], suma[1], suma[2], suma[3]); __syncthreads();
    for (int s = 128; s > 0; s >>= 1) {
        if (t < s) {
            float4 o = red4[t + s];
            red4[t].x += o.x; red4[t].y += o.y; red4[t].z += o.z; red4[t].w += o.w;
        }
        __syncthreads();
    }
    float4 sum = red4[0];
    float inv[4] = {1.f / sum.x, 1.f / sum.y, 1.f / sum.z, 1.f / sum.w};

    if (!isfixed) {
#pragma unroll
        for (int jj = 0; jj < 8; jj++) {
            int j = t + jj * 256;
            if (j < NN)
#pragma unroll
                for (int r = 0; r < 4; r++)
                    g_Sh[(size_t)(i0 + r) * KPAD + j] = __float2half(vals[r][jj] * inv[r]);
        }
    } else {
#pragma unroll
        for (int jj = 0; jj < 8; jj++) {
            int j = t + jj * 256;
            if (j < NN)
#pragma unroll
                for (int r = 0; r < 4; r++)
                    g_S[(size_t)(i0 + r) * NN + j] = vals[r][jj];
        }
        if (t < 4) g_rrow[i0 + t] = inv[t];
    }
}

// fixed-adj path only: column j scaled by 1/rowsum[j], emit fp16
__global__ void kColDivH(const int* __restrict__ fixedp) {
    if (decode_scalar(fixedp) == 0.0f) return;
    int idx = blockIdx.x * blockDim.x + threadIdx.x;
    int stride = gridDim.x * blockDim.x;
    for (; idx < NN * NN; idx += stride) {
        int i = idx / NN, j = idx - i * NN;
        g_Sh[(size_t)i * KPAD + j] = __float2half(g_S[idx] * g_rrow[j]);
    }
}

// ---------------- prep: bias/wws/wwt + gnn rowsum + temporal + packT ----------------
__global__ __launch_bounds__(256) void kPrep(const float* __restrict__ ne,
                                             const float* __restrict__ bp,
                                             const float* __restrict__ wwsp,
                                             const float* __restrict__ wwtp,
                                             const float* __restrict__ gw,
                                             const float* __restrict__ xwin,
                                             const float* __restrict__ Tp,
                                             const float* __restrict__ x) {
    __shared__ float nn[16];
    __shared__ float red[256];
    int n = blockIdx.x, t = threadIdx.x;
    if (t < 16) nn[t] = ne[n * DD + t];
    __syncthreads();
    {
        float acc = 0.f;
#pragma unroll
        for (int d = 0; d < 16; d++) acc += nn[d] * bp[d * OO + t];
        g_bias[n * OO + t] = acc;
    }
    if (t < O8) {
        float a = 0.f;
#pragma unroll
        for (int d = 0; d < 16; d++) a += nn[d] * wwsp[d * O8 + t];
        g_wws[n * O8 + t] = a;
    }
    if (t < O2) {
        float a = 0.f;
#pragma unroll
        for (int d = 0; d < 16; d++) a += nn[d] * wwtp[d * O2 + t];
        g_wwt[n * O2 + t] = a;
    }
    {
        float s = 0.f;
        for (int j = t; j < NN; j += 256) s += gw[(size_t)n * NN + j];
        red[t] = s; __syncthreads();
        for (int st = 128; st > 0; st >>= 1) { if (t < st) red[t] += red[t + st]; __syncthreads(); }
        if (t == 0) g_rsum[n] = red[0];
    }
    if (t < BB) {
        float s = 0.f;
#pragma unroll
        for (int w = 0; w < WW; w++) s += xwin[(size_t)t * WW * NN + (size_t)w * NN + n] * Tp[w];
        g_xw[t * NN + n] = s;
    }
    for (int l = t; l < BC; l += 256) {
        int b = l / CC, c = l - b * CC;
        g_XtT[(size_t)l * KPAD + n] = __float2half(x[(size_t)(b * NN + n) * CC + c]);
    }
}

// ---------------- fp16 MMA GEMM, ldmatrix + double buffer: C(2000,320) = S @ B ----------------
__global__ __launch_bounds__(256) void kGemmMMA(int phase) {
    const __half* __restrict__ Bt = phase ? g_Y1T : g_XtT;
    float* __restrict__ Y = phase ? g_Y2 : g_Y1;
    __shared__ __half As[2][64][72];
    __shared__ __half Bs[2][64][72];
    int m0 = blockIdx.x * 64, n0 = blockIdx.y * 64;
    int t = threadIdx.x;
    int wid = t >> 5, lane = t & 31;
    int wm = (wid & 3) * 16, wn = (wid >> 2) * 32;
    float acc[4][4] = {};

    // global loader mapping (uint4 = 8 halves)
    int row0 = t >> 3, seg = t & 7;
    int row1 = row0 + 32;
    int gmA0 = m0 + row0; if (gmA0 > NN - 1) gmA0 = NN - 1;
    int gmA1 = m0 + row1; if (gmA1 > NN - 1) gmA1 = NN - 1;
    const __half* a0p = &g_Sh[(size_t)gmA0 * KPAD + seg * 8];
    const __half* a1p = &g_Sh[(size_t)gmA1 * KPAD + seg * 8];
    const __half* b0p = &Bt[(size_t)(n0 + row0) * KPAD + seg * 8];
    const __half* b1p = &Bt[(size_t)(n0 + row1) * KPAD + seg * 8];

    // ldmatrix base addresses
    int r = lane & 7, f = lane >> 3;
    // A frag order: (+0,+0) (+8,+0) (+0,+8) (+8,+8)
    int a_row = wm + ((f & 1) << 3) + r;
    int a_col = (f >> 1) << 3;
    unsigned aB0 = cvta_s(&As[0][a_row][a_col]);
    unsigned aB1 = cvta_s(&As[1][a_row][a_col]);
    // B frag order for nj pair: (nj_even, k0) (nj_even, k8) (nj_odd, k0) (nj_odd, k8)
    int b_row = wn + ((f >> 1) << 3) + r;
    int b_col = (f & 1) << 3;
    unsigned bB0 = cvta_s(&Bs[0][b_row][b_col]);
    unsigned bB1 = cvta_s(&Bs[1][b_row][b_col]);

    // preload kc=0
    uint4 av0 = *(const uint4*)(a0p);
    uint4 av1 = *(const uint4*)(a1p);
    uint4 bv0 = *(const uint4*)(b0p);
    uint4 bv1 = *(const uint4*)(b1p);
    *(uint4*)&As[0][row0][seg * 8] = av0;
    *(uint4*)&As[0][row1][seg * 8] = av1;
    *(uint4*)&Bs[0][row0][seg * 8] = bv0;
    *(uint4*)&Bs[0][row1][seg * 8] = bv1;
    __syncthreads();

    for (int kc = 0; kc < KPAD / 64; kc++) {
        int cur = kc & 1;
        if (kc + 1 < KPAD / 64) {
            size_t off = (size_t)(kc + 1) * 64;
            av0 = *(const uint4*)(a0p + off);
            av1 = *(const uint4*)(a1p + off);
            bv0 = *(const uint4*)(b0p + off);
            bv1 = *(const uint4*)(b1p + off);
        }
        unsigned aB = cur ? aB1 : aB0;
        unsigned bB = cur ? bB1 : bB0;
#pragma unroll
        for (int ks = 0; ks < 4; ks++) {
            unsigned a0, a1, a2, a3;
            asm volatile("ldmatrix.sync.aligned.m8n8.x4.shared.b16 {%0,%1,%2,%3}, [%4];"
                         : "=r"(a0), "=r"(a1), "=r"(a2), "=r"(a3)
                         : "r"(aB + ks * 32));
            unsigned b00, b01, b10, b11;
            asm volatile("ldmatrix.sync.aligned.m8n8.x4.shared.b16 {%0,%1,%2,%3}, [%4];"
                         : "=r"(b00), "=r"(b01), "=r"(b10), "=r"(b11)
                         : "r"(bB + ks * 32));
            unsigned b20, b21, b30, b31;
            asm volatile("ldmatrix.sync.aligned.m8n8.x4.shared.b16 {%0,%1,%2,%3}, [%4];"
                         : "=r"(b20), "=r"(b21), "=r"(b30), "=r"(b31)
                         : "r"(bB + ks * 32 + 16 * 144));
#define MMA16816(ACC, B0, B1) \
            asm volatile("mma.sync.aligned.m16n8k16.row.col.f32.f16.f16.f32 " \
                "{%0,%1,%2,%3}, {%4,%5,%6,%7}, {%8,%9}, {%0,%1,%2,%3};" \
                : "+f"(ACC[0]), "+f"(ACC[1]), "+f"(ACC[2]), "+f"(ACC[3]) \
                : "r"(a0), "r"(a1), "r"(a2), "r"(a3), "r"(B0), "r"(B1))
            MMA16816(acc[0], b00, b01);
            MMA16816(acc[1], b10, b11);
            MMA16816(acc[2], b20, b21);
            MMA16816(acc[3], b30, b31);
#undef MMA16816
        }
        if (kc + 1 < KPAD / 64) {
            int nxt = cur ^ 1;
            *(uint4*)&As[nxt][row0][seg * 8] = av0;
            *(uint4*)&As[nxt][row1][seg * 8] = av1;
            *(uint4*)&Bs[nxt][row0][seg * 8] = bv0;
            *(uint4*)&Bs[nxt][row1][seg * 8] = bv1;
        }
        __syncthreads();
    }

    int grp = lane >> 2, tid4 = lane & 3;
    int r0 = m0 + wm + grp, r1 = r0 + 8;
#pragma unroll
    for (int nj = 0; nj < 4; nj++) {
        int col = n0 + wn + nj * 8 + tid4 * 2;
        if (r0 < NN) {
            *(float2*)&Y[(size_t)r0 * NCP + col] = make_float2(acc[nj][0], acc[nj][1]);
            if (phase == 0) {
                g_Y1T[(size_t)col * KPAD + r0]       = __float2half(acc[nj][0]);
                g_Y1T[(size_t)(col + 1) * KPAD + r0] = __float2half(acc[nj][1]);
            }
        }
        if (r1 < NN) {
            *(float2*)&Y[(size_t)r1 * NCP + col] = make_float2(acc[nj][2], acc[nj][3]);
            if (phase == 0) {
                g_Y1T[(size_t)col * KPAD + r1]       = __float2half(acc[nj][2]);
                g_Y1T[(size_t)(col + 1) * KPAD + r1] = __float2half(acc[nj][3]);
            }
        }
    }
}

// ---------------- adaptive weights (fp16 out): W[n,kc,o] = sum_d ne[n,d] wp[d,kc,o] ----------------
__global__ void kWeights(const float* __restrict__ ne, const float* __restrict__ wp) {
    __shared__ float nes[32][17];
    int j0 = blockIdx.x * 256;
    int n0 = blockIdx.y * 32;
    int t = threadIdx.x;
    for (int l = t; l < 32 * 16; l += 256) {
        int r = l >> 4, d = l & 15;
        nes[r][d] = (n0 + r < NN) ? ne[(n0 + r) * DD + d] : 0.f;
    }
    __syncthreads();
    int j = j0 + t;
    if (j < KCQ * O4) {
        float w[16];
#pragma unroll
        for (int d = 0; d < 16; d++) w[d] = wp[d * (KCQ * O4) + j];
        for (int r = 0; r < 32; r++) {
            int n = n0 + r;
            if (n >= NN) break;
            float acc = 0.f;
#pragma unroll
            for (int d = 0; d < 16; d++) acc += nes[r][d] * w[d];
            g_Wh[(size_t)n * (KCQ * O4) + j] = __float2half(acc);
        }
    }
}

// ---------------- hodge: se + mpT init (jump*te) ----------------
__global__ void kH1(const float* __restrict__ xew, const int* __restrict__ bidx,
                    const float* __restrict__ lw, const float* __restrict__ lb,
                    const int* __restrict__ jumpp) {
    int idx = blockIdx.x * blockDim.x + threadIdx.x;
    if (idx >= BB * NE) return;
    int b = idx / NE, i = idx % NE;
    float w0 = lw[0], b0 = lb[0];
    float jc = decode_scalar(jumpp);
    float s = 0.f, tt = 0.f;
#pragma unroll
    for (int f = 0; f < NBB; f++) {
        int wv = bidx[f];
        float v = xew[(size_t)b * WW * NE + (size_t)wv * NE + i] * w0 + b0;
        s += v;
        tt += (float)(NBB - 1 - f) * v;
    }
    g_se[idx] = s;
    g_mpT[i * BB + b] = jc * tt;
}

__global__ void kH2(const float* __restrict__ hodge) {
    __shared__ float ses[16][251];
    int j0 = blockIdx.x * 128;
    int i0 = blockIdx.y * 250;
    int t = threadIdx.x;
    for (int l = t; l < 16 * 250; l += 128) {
        int b = l / 250, ii = l % 250;
        ses[b][ii] = g_se[b * NE + i0 + ii];
    }
    __syncthreads();
    int j = j0 + t;
    if (j < NE) {
        float acc[16] = {};
        for (int ii = 0; ii < 250; ii++) {
            float h = hodge[(size_t)(i0 + ii) * NE + j];
#pragma unroll
            for (int b = 0; b < 16; b++) acc[b] += ses[b][ii] * h;
        }
#pragma unroll
        for (int b = 0; b < 16; b++) atomicAdd(&g_mpT[j * BB + b], acc[b]);
    }
}

// xm[n,b] = (1/nb) sum_e mpT[e,b] * inc[n,e]
__global__ void kH3(const float* __restrict__ inc, int nb) {
    __shared__ float incs[16][65];
    __shared__ float mps[64][17];
    int n0 = blockIdx.x * 16;
    int t = threadIdx.x;
    int nr = t >> 4, b = t & 15;
    float acc = 0.f;
    for (int e0 = 0; e0 < NE; e0 += 64) {
        for (int l = t; l < 1024; l += 256) {
            int r = l >> 6, ee = l & 63;
            int e = e0 + ee;
            incs[r][ee] = (e < NE) ? inc[(size_t)(n0 + r) * NE + e] : 0.f;
        }
        for (int l = t; l < 1024; l += 256) {
            int ee = l >> 4, bb = l & 15;
            int e = e0 + ee;
            mps[ee][bb] = (e < NE) ? g_mpT[e * BB + bb] : 0.f;
        }
        __syncthreads();
#pragma unroll 8
        for (int ee = 0; ee < 64; ee++) acc += incs[nr][ee] * mps[ee][b];
        __syncthreads();
    }
    g_xm[(n0 + nr) * BB + b] = acc / (float)nb;
}

// ---------------- fused output: diffusion (0:64) + ZFC/temporal/supra (64:256) ----------------
__global__ __launch_bounds__(256) void kOut(const float* __restrict__ x,
                                            const float* __restrict__ zin,
                                            const float* __restrict__ gnnb,
                                            float* __restrict__ out) {
    __shared__ float ws[KCQ * O4];
    __shared__ float xs[BB][KCQ + 1];
    int n = blockIdx.x, t = threadIdx.x;
    for (int l = t; l < KCQ * O4; l += 256)
        ws[l] = __half2float(g_Wh[(size_t)n * (KCQ * O4) + l]);
    for (int l = t; l < BB * KCQ; l += 256) {
        int b = l / KCQ, kc = l % KCQ;
        int k = kc / CC, c = kc % CC;
        float v;
        if (k == 0)      v = x[(size_t)(b * NN + n) * CC + c];
        else if (k == 1) v = g_Y1[(size_t)n * NCP + b * CC + c];
        else             v = g_Y2[(size_t)n * NCP + b * CC + c];
        xs[b][kc] = v;
    }
    __syncthreads();
    // phase A: diffusion channels 0..63 (all 256 threads)
    {
        int o = t & 63, bq = t >> 6;
        int b0 = bq * 4;
        float a0 = 0.f, a1 = 0.f, a2 = 0.f, a3 = 0.f;
        for (int kc = 0; kc < KCQ; kc++) {
            float w = ws[kc * O4 + o];
            a0 += xs[b0 + 0][kc] * w;
            a1 += xs[b0 + 1][kc] * w;
            a2 += xs[b0 + 2][kc] * w;
            a3 += xs[b0 + 3][kc] * w;
        }
        float bi = g_bias[n * OO + o];
        out[(size_t)((b0 + 0) * NN + n) * OO + o] = a0 + bi;
        out[(size_t)((b0 + 1) * NN + n) * OO + o] = a1 + bi;
        out[(size_t)((b0 + 2) * NN + n) * OO + o] = a2 + bi;
        out[(size_t)((b0 + 3) * NN + n) * OO + o] = a3 + bi;
    }
    // phase B: channels 64..255 (threads 0..191; no smem dependency)
    if (t < 192) {
        int j = t, o;
        int q = 0; float zr = 0.f, gb = 0.f, wwtv = 0.f, wwsv = 0.f;
        if (j < 32) {
            int k = n * 32 + j;
            q = k / NN; int m = k - q * NN;
            zr = g_rsum[m]; gb = gnnb[m];
            o = 64 + j;
        } else if (j < 160) {
            wwtv = g_wwt[n * O2 + (j - 32)];
            o = 96 + (j - 32);
        } else {
            wwsv = g_wws[n * O8 + (j - 160)];
            o = 224 + (j - 160);
        }
        float bi = g_bias[n * OO + o];
#pragma unroll
        for (int b = 0; b < BB; b++) {
            float v;
            if (j < 32)       v = fmaxf(zin[b * 32 + q] * zr + gb, 0.f);
            else if (j < 160) v = g_xw[b * NN + n] * wwtv;
            else              v = g_xm[n * BB + b] * wwsv;
            out[(size_t)(b * NN + n) * OO + o] = v + bi;
        }
    }
}

// ---------------- launch ----------------
extern "C" void kernel_launch(void* const* d_in, const int* in_sizes, int n_in,
                              void* d_out, int out_size) {
    const float* x     = (const float*)d_in[0];
    const float* xwin  = (const float*)d_in[1];
    const float* ne    = (const float*)d_in[2];
    const int*   fixed = (const int*)  d_in[3];
    const float* adj   = (const float*)d_in[4];
    const int*   stay  = (const int*)  d_in[5];
    const int*   jump  = (const int*)  d_in[6];
    const float* zin   = (const float*)d_in[7];
    const float* hodge = (const float*)d_in[8];
    const float* xew   = (const float*)d_in[9];
    const float* inc   = (const float*)d_in[10];
    const float* wp    = (const float*)d_in[11];
    const float* wwsp  = (const float*)d_in[12];
    const float* wwtp  = (const float*)d_in[13];
    const float* bp    = (const float*)d_in[14];
    const float* Tp    = (const float*)d_in[15];
    const float* lw    = (const float*)d_in[16];
    const float* lb    = (const float*)d_in[17];
    const float* gw    = (const float*)d_in[18];
    const float* gnnb  = (const float*)d_in[19];
    const int*   bidx  = (const int*)  d_in[20];
    float* out = (float*)d_out;
    int nb = in_sizes[20];   // NB = 3

    kS0Softmax<<<500, 256>>>(ne, adj, stay, fixed);
    kColDivH<<<256, 256>>>(fixed);           // dead on softmax path

    kPrep<<<NN, 256>>>(ne, bp, wwsp, wwtp, gw, xwin, Tp, x);

    kGemmMMA<<<dim3(32, 5), 256>>>(0);
    kGemmMMA<<<dim3(32, 5), 256>>>(1);

    kWeights<<<dim3(13, 63), 256>>>(ne, wp);

    kH1<<<(BB * NE + 255) / 256, 256>>>(xew, bidx, lw, lb, jump);
    kH2<<<dim3(24, 12), 128>>>(hodge);
    kH3<<<125, 256>>>(inc, nb);

    kOut<<<NN, 256>>>(x, zin, gnnb, out);
}

// round 7
// speedup vs baseline: 1.7580x; 1.0348x over previous
#include <cuda_runtime.h>
#include <cuda_fp16.h>
#include <math.h>

// Problem dims
#define NN   2000
#define NE   3000
#define BB   16
#define CC   17
#define WW   12
#define DD   16
#define OO   256
#define KK   3
#define NBB  3
#define BC   (BB*CC)    // 272
#define NCP  320        // fp32 Y stride
#define KPAD 2048       // fp16 padded k-stride (zero-init padding is load-bearing)
#define KCQ  (KK*CC)    // 51
#define O4   64
#define O8   32
#define O2   128

#define STAGES 4
#define TILE_HALVES (64*72)            // one A or B tile in halves
#define STAGE_BYTES (2*TILE_HALVES*2)  // A+B per stage = 18432 B
#define GEMM_SMEM   (STAGES*STAGE_BYTES) // 73728 B

// ---------------- scratch (device globals; no runtime alloc) ----------------
__device__ float g_S[NN*NN];                 // fixed-adj path only
__device__ __half g_Sh[NN*KPAD];             // fp16 S (pad cols zero)
__device__ __half g_XtT[NCP*KPAD];           // fp16 X^T rows n=b*17+c, cols m
__device__ __half g_Y1T[NCP*KPAD];           // fp16 Y1^T
__device__ float g_rrow[NN];
__device__ float g_Y1[NN*NCP];
__device__ float g_Y2[NN*NCP];
__device__ __half g_Wh[NN*KCQ*O4];           // adaptive weights (fp16, 13 MB)
__device__ float g_bias[NN*OO];
__device__ float g_wws[NN*O8];
__device__ float g_wwt[NN*O2];
__device__ float g_xw[BB*NN];
__device__ float g_se[BB*NE];
__device__ float g_mpT[NE*BB];
__device__ float g_xm[NN*BB];
__device__ float g_rsum[NN];

__device__ __forceinline__ float decode_scalar(const int* p) {
    int iv = *p;
    return (iv > -1000000 && iv < 1000000) ? (float)iv : __int_as_float(iv);
}

__device__ __forceinline__ unsigned cvta_s(const void* p) {
    return (unsigned)__cvta_generic_to_shared(p);
}

// ---------------- fused: S0 = relu(ne@ne^T) diag=stay, softmax -> fp16 S ----------------
__global__ __launch_bounds__(256) void kS0Softmax(const float* __restrict__ ne,
                                                  const float* __restrict__ adj,
                                                  const int* __restrict__ stay,
                                                  const int* __restrict__ fixedp) {
    __shared__ float4 red4[256];
    int i0 = blockIdx.x * 4;
    int t = threadIdx.x;
    bool isfixed = (decode_scalar(fixedp) != 0.0f);
    float sc = decode_scalar(stay);

    float nei[4][16];
#pragma unroll
    for (int r = 0; r < 4; r++)
#pragma unroll
        for (int q = 0; q < 4; q++) {
            float4 v = __ldg((const float4*)&ne[(size_t)(i0 + r) * DD + q * 4]);
            nei[r][q * 4 + 0] = v.x; nei[r][q * 4 + 1] = v.y;
            nei[r][q * 4 + 2] = v.z; nei[r][q * 4 + 3] = v.w;
        }

    float vals[4][8];
    float4 mx = make_float4(-1e30f, -1e30f, -1e30f, -1e30f);
#pragma unroll
    for (int jj = 0; jj < 8; jj++) {
        int j = t + jj * 256;
        if (j < NN) {
            float nej[16];
#pragma unroll
            for (int q = 0; q < 4; q++) {
                float4 v = __ldg((const float4*)&ne[(size_t)j * DD + q * 4]);
                nej[q * 4 + 0] = v.x; nej[q * 4 + 1] = v.y;
                nej[q * 4 + 2] = v.z; nej[q * 4 + 3] = v.w;
            }
#pragma unroll
            for (int r = 0; r < 4; r++) {
                float acc = 0.f;
#pragma unroll
                for (int d = 0; d < 16; d++) acc += nei[r][d] * nej[d];
                vals[r][jj] = (j == i0 + r) ? sc : fmaxf(acc, 0.f);
            }
            mx.x = fmaxf(mx.x, vals[0][jj]); mx.y = fmaxf(mx.y, vals[1][jj]);
            mx.z = fmaxf(mx.z, vals[2][jj]); mx.w = fmaxf(mx.w, vals[3][jj]);
        } else {
#pragma unroll
            for (int r = 0; r < 4; r++) vals[r][jj] = -1e30f;
        }
    }
    red4[t] = mx; __syncthreads();
    for (int s = 128; s > 0; s >>= 1) {
        if (t < s) {
            float4 o = red4[t + s];
            red4[t].x = fmaxf(red4[t].x, o.x); red4[t].y = fmaxf(red4[t].y, o.y);
            red4[t].z = fmaxf(red4[t].z, o.z); red4[t].w = fmaxf(red4[t].w, o.w);
        }
        __syncthreads();
    }
    mx = red4[0]; __syncthreads();
    float mxa[4] = {mx.x, mx.y, mx.z, mx.w};

    float suma[4] = {0.f, 0.f, 0.f, 0.f};
#pragma unroll
    for (int jj = 0; jj < 8; jj++) {
        int j = t + jj * 256;
        if (j < NN) {
#pragma unroll
            for (int r = 0; r < 4; r++) {
                float e;
                if (!isfixed) e = expf(vals[r][jj] - mxa[r]);
                else          e = __ldg(&adj[(size_t)(i0 + r) * NN + j]) * expf(vals[r][jj]);
                vals[r][jj] = e;
                suma[r] += e;
            }
        }
    }
    red4[t] = make_float4(suma[0], suma[1], suma[2], suma[3]); __syncthreads();
    for (int s = 128; s > 0; s >>= 1) {
        if (t < s) {
            float4 o = red4[t + s];
            red4[t].x += o.x; red4[t].y += o.y; red4[t].z += o.z; red4[t].w += o.w;
        }
        __syncthreads();
    }
    float4 sum = red4[0];
    float inv[4] = {1.f / sum.x, 1.f / sum.y, 1.f / sum.z, 1.f / sum.w};

    if (!isfixed) {
#pragma unroll
        for (int jj = 0; jj < 8; jj++) {
            int j = t + jj * 256;
            if (j < NN)
#pragma unroll
                for (int r = 0; r < 4; r++)
                    g_Sh[(size_t)(i0 + r) * KPAD + j] = __float2half(vals[r][jj] * inv[r]);
        }
    } else {
#pragma unroll
        for (int jj = 0; jj < 8; jj++) {
            int j = t + jj * 256;
            if (j < NN)
#pragma unroll
                for (int r = 0; r < 4; r++)
                    g_S[(size_t)(i0 + r) * NN + j] = vals[r][jj];
        }
        if (t < 4) g_rrow[i0 + t] = inv[t];
    }
}

// fixed-adj path only: column j scaled by 1/rowsum[j], emit fp16
__global__ void kColDivH(const int* __restrict__ fixedp) {
    if (decode_scalar(fixedp) == 0.0f) return;
    int idx = blockIdx.x * blockDim.x + threadIdx.x;
    int stride = gridDim.x * blockDim.x;
    for (; idx < NN * NN; idx += stride) {
        int i = idx / NN, j = idx - i * NN;
        g_Sh[(size_t)i * KPAD + j] = __float2half(g_S[idx] * g_rrow[j]);
    }
}

// ---------------- prep: bias/wws/wwt + gnn rowsum + temporal + packT + hodge se/mpT ----------------
__global__ __launch_bounds__(256) void kPrep(const float* __restrict__ ne,
                                             const float* __restrict__ bp,
                                             const float* __restrict__ wwsp,
                                             const float* __restrict__ wwtp,
                                             const float* __restrict__ gw,
                                             const float* __restrict__ xwin,
                                             const float* __restrict__ Tp,
                                             const float* __restrict__ x,
                                             const float* __restrict__ xew,
                                             const int* __restrict__ bidx,
                                             const float* __restrict__ lw,
                                             const float* __restrict__ lb,
                                             const int* __restrict__ jumpp) {
    __shared__ float nn[16];
    __shared__ float red[256];
    int n = blockIdx.x, t = threadIdx.x;
    if (t < 16) nn[t] = ne[n * DD + t];
    __syncthreads();
    {
        float acc = 0.f;
#pragma unroll
        for (int d = 0; d < 16; d++) acc += nn[d] * bp[d * OO + t];
        g_bias[n * OO + t] = acc;
    }
    if (t < O8) {
        float a = 0.f;
#pragma unroll
        for (int d = 0; d < 16; d++) a += nn[d] * wwsp[d * O8 + t];
        g_wws[n * O8 + t] = a;
    }
    if (t < O2) {
        float a = 0.f;
#pragma unroll
        for (int d = 0; d < 16; d++) a += nn[d] * wwtp[d * O2 + t];
        g_wwt[n * O2 + t] = a;
    }
    {
        float s = 0.f;
        for (int j = t; j < NN; j += 256) s += gw[(size_t)n * NN + j];
        red[t] = s; __syncthreads();
        for (int st = 128; st > 0; st >>= 1) { if (t < st) red[t] += red[t + st]; __syncthreads(); }
        if (t == 0) g_rsum[n] = red[0];
    }
    if (t < BB) {
        float s = 0.f;
#pragma unroll
        for (int w = 0; w < WW; w++) s += xwin[(size_t)t * WW * NN + (size_t)w * NN + n] * Tp[w];
        g_xw[t * NN + n] = s;
    }
    for (int l = t; l < BC; l += 256) {
        int b = l / CC, c = l - b * CC;
        g_XtT[(size_t)l * KPAD + n] = __float2half(x[(size_t)(b * NN + n) * CC + c]);
    }
    // hodge se + mpT init (folded former kH1): one element per global thread
    {
        int gid = n * 256 + t;
        if (gid < BB * NE) {
            int b = gid / NE, i = gid - b * NE;
            float w0 = lw[0], b0 = lb[0];
            float jc = decode_scalar(jumpp);
            float s = 0.f, tt = 0.f;
#pragma unroll
            for (int f = 0; f < NBB; f++) {
                int wv = bidx[f];
                float v = xew[(size_t)b * WW * NE + (size_t)wv * NE + i] * w0 + b0;
                s += v;
                tt += (float)(NBB - 1 - f) * v;
            }
            g_se[gid] = s;
            g_mpT[i * BB + b] = jc * tt;
        }
    }
}

// ---------------- fp16 MMA GEMM, cp.async 4-stage pipeline: C(2000,320) = S @ B ----------------
__global__ __launch_bounds__(256) void kGemmMMA(int phase) {
    extern __shared__ __half sm[];
    const __half* __restrict__ Bt = phase ? g_Y1T : g_XtT;
    float* __restrict__ Y = phase ? g_Y2 : g_Y1;
    int m0 = blockIdx.x * 64, n0 = blockIdx.y * 64;
    int t = threadIdx.x;
    int wid = t >> 5, lane = t & 31;
    int wm = (wid & 3) * 16, wn = (wid >> 2) * 32;
    float acc[4][4] = {};

    // loader mapping: 16B per thread per tile-half
    int row0 = t >> 3, seg = t & 7;
    int row1 = row0 + 32;
    int gmA0 = m0 + row0; if (gmA0 > NN - 1) gmA0 = NN - 1;
    int gmA1 = m0 + row1; if (gmA1 > NN - 1) gmA1 = NN - 1;
    const __half* a0p = &g_Sh[(size_t)gmA0 * KPAD + seg * 8];
    const __half* a1p = &g_Sh[(size_t)gmA1 * KPAD + seg * 8];
    const __half* b0p = &Bt[(size_t)(n0 + row0) * KPAD + seg * 8];
    const __half* b1p = &Bt[(size_t)(n0 + row1) * KPAD + seg * 8];

    unsigned smb = cvta_s(sm);
    unsigned dA0 = smb + (row0 * 72 + seg * 8) * 2;
    unsigned dA1 = smb + (row1 * 72 + seg * 8) * 2;
    unsigned dB0 = dA0 + TILE_HALVES * 2;
    unsigned dB1 = dA1 + TILE_HALVES * 2;

    // ldmatrix fragment addresses
    int r = lane & 7, f = lane >> 3;
    unsigned aOff = smb + ((wm + ((f & 1) << 3) + r) * 72 + ((f >> 1) << 3)) * 2;
    unsigned bOff = smb + TILE_HALVES * 2 + ((wn + ((f >> 1) << 3) + r) * 72 + ((f & 1) << 3)) * 2;

#define ISSUE(KC) do {                                                          \
    if ((KC) < KPAD / 64) {                                                     \
        unsigned sb_ = ((KC) & (STAGES - 1)) * STAGE_BYTES;                     \
        size_t off_ = (size_t)(KC) * 64;                                        \
        asm volatile("cp.async.cg.shared.global [%0], [%1], 16;" :: "r"(dA0 + sb_), "l"(a0p + off_)); \
        asm volatile("cp.async.cg.shared.global [%0], [%1], 16;" :: "r"(dA1 + sb_), "l"(a1p + off_)); \
        asm volatile("cp.async.cg.shared.global [%0], [%1], 16;" :: "r"(dB0 + sb_), "l"(b0p + off_)); \
        asm volatile("cp.async.cg.shared.global [%0], [%1], 16;" :: "r"(dB1 + sb_), "l"(b1p + off_)); \
    }                                                                           \
    asm volatile("cp.async.commit_group;");                                     \
} while (0)

    ISSUE(0); ISSUE(1); ISSUE(2);

    for (int kc = 0; kc < KPAD / 64; kc++) {
        asm volatile("cp.async.wait_group %0;" :: "n"(STAGES - 2));
        __syncthreads();
        ISSUE(kc + 3);
        unsigned sb = (kc & (STAGES - 1)) * STAGE_BYTES;
        unsigned aB = aOff + sb, bB = bOff + sb;
#pragma unroll
        for (int ks = 0; ks < 4; ks++) {
            unsigned a0, a1, a2, a3;
            asm volatile("ldmatrix.sync.aligned.m8n8.x4.shared.b16 {%0,%1,%2,%3}, [%4];"
                         : "=r"(a0), "=r"(a1), "=r"(a2), "=r"(a3)
                         : "r"(aB + ks * 32));
            unsigned b00, b01, b10, b11;
            asm volatile("ldmatrix.sync.aligned.m8n8.x4.shared.b16 {%0,%1,%2,%3}, [%4];"
                         : "=r"(b00), "=r"(b01), "=r"(b10), "=r"(b11)
                         : "r"(bB + ks * 32));
            unsigned b20, b21, b30, b31;
            asm volatile("ldmatrix.sync.aligned.m8n8.x4.shared.b16 {%0,%1,%2,%3}, [%4];"
                         : "=r"(b20), "=r"(b21), "=r"(b30), "=r"(b31)
                         : "r"(bB + ks * 32 + 16 * 144));
#define MMA16816(ACC, B0, B1) \
            asm volatile("mma.sync.aligned.m16n8k16.row.col.f32.f16.f16.f32 " \
                "{%0,%1,%2,%3}, {%4,%5,%6,%7}, {%8,%9}, {%0,%1,%2,%3};" \
                : "+f"(ACC[0]), "+f"(ACC[1]), "+f"(ACC[2]), "+f"(ACC[3]) \
                : "r"(a0), "r"(a1), "r"(a2), "r"(a3), "r"(B0), "r"(B1))
            MMA16816(acc[0], b00, b01);
            MMA16816(acc[1], b10, b11);
            MMA16816(acc[2], b20, b21);
            MMA16816(acc[3], b30, b31);
#undef MMA16816
        }
    }
#undef ISSUE

    int grp = lane >> 2, tid4 = lane & 3;
    int r0 = m0 + wm + grp, r1 = r0 + 8;
#pragma unroll
    for (int nj = 0; nj < 4; nj++) {
        int col = n0 + wn + nj * 8 + tid4 * 2;
        if (r0 < NN) {
            *(float2*)&Y[(size_t)r0 * NCP + col] = make_float2(acc[nj][0], acc[nj][1]);
            if (phase == 0) {
                g_Y1T[(size_t)col * KPAD + r0]       = __float2half(acc[nj][0]);
                g_Y1T[(size_t)(col + 1) * KPAD + r0] = __float2half(acc[nj][1]);
            }
        }
        if (r1 < NN) {
            *(float2*)&Y[(size_t)r1 * NCP + col] = make_float2(acc[nj][2], acc[nj][3]);
            if (phase == 0) {
                g_Y1T[(size_t)col * KPAD + r1]       = __float2half(acc[nj][2]);
                g_Y1T[(size_t)(col + 1) * KPAD + r1] = __float2half(acc[nj][3]);
            }
        }
    }
}

// ---------------- adaptive weights (fp16 out): W[n,kc,o] = sum_d ne[n,d] wp[d,kc,o] ----------------
__global__ void kWeights(const float* __restrict__ ne, const float* __restrict__ wp) {
    __shared__ float nes[32][17];
    int j0 = blockIdx.x * 256;
    int n0 = blockIdx.y * 32;
    int t = threadIdx.x;
    for (int l = t; l < 32 * 16; l += 256) {
        int r = l >> 4, d = l & 15;
        nes[r][d] = (n0 + r < NN) ? ne[(n0 + r) * DD + d] : 0.f;
    }
    __syncthreads();
    int j = j0 + t;
    if (j < KCQ * O4) {
        float w[16];
#pragma unroll
        for (int d = 0; d < 16; d++) w[d] = wp[d * (KCQ * O4) + j];
        for (int r = 0; r < 32; r++) {
            int n = n0 + r;
            if (n >= NN) break;
            float acc = 0.f;
#pragma unroll
            for (int d = 0; d < 16; d++) acc += nes[r][d] * w[d];
            g_Wh[(size_t)n * (KCQ * O4) + j] = __float2half(acc);
        }
    }
}

__global__ void kH2(const float* __restrict__ hodge) {
    __shared__ float ses[16][251];
    int j0 = blockIdx.x * 128;
    int i0 = blockIdx.y * 250;
    int t = threadIdx.x;
    for (int l = t; l < 16 * 250; l += 128) {
        int b = l / 250, ii = l % 250;
        ses[b][ii] = g_se[b * NE + i0 + ii];
    }
    __syncthreads();
    int j = j0 + t;
    if (j < NE) {
        float acc[16] = {};
        for (int ii = 0; ii < 250; ii++) {
            float h = hodge[(size_t)(i0 + ii) * NE + j];
#pragma unroll
            for (int b = 0; b < 16; b++) acc[b] += ses[b][ii] * h;
        }
#pragma unroll
        for (int b = 0; b < 16; b++) atomicAdd(&g_mpT[j * BB + b], acc[b]);
    }
}

// xm[n,b] = (1/nb) sum_e mpT[e,b] * inc[n,e]
__global__ void kH3(const float* __restrict__ inc, int nb) {
    __shared__ float incs[16][65];
    __shared__ float mps[64][17];
    int n0 = blockIdx.x * 16;
    int t = threadIdx.x;
    int nr = t >> 4, b = t & 15;
    float acc = 0.f;
    for (int e0 = 0; e0 < NE; e0 += 64) {
        for (int l = t; l < 1024; l += 256) {
            int r = l >> 6, ee = l & 63;
            int e = e0 + ee;
            incs[r][ee] = (e < NE) ? inc[(size_t)(n0 + r) * NE + e] : 0.f;
        }
        for (int l = t; l < 1024; l += 256) {
            int ee = l >> 4, bb = l & 15;
            int e = e0 + ee;
            mps[ee][bb] = (e < NE) ? g_mpT[e * BB + bb] : 0.f;
        }
        __syncthreads();
#pragma unroll 8
        for (int ee = 0; ee < 64; ee++) acc += incs[nr][ee] * mps[ee][b];
        __syncthreads();
    }
    g_xm[(n0 + nr) * BB + b] = acc / (float)nb;
}

// ---------------- fused output: diffusion (0:64) + ZFC/temporal/supra (64:256) ----------------
__global__ __launch_bounds__(256) void kOut(const float* __restrict__ x,
                                            const float* __restrict__ zin,
                                            const float* __restrict__ gnnb,
                                            float* __restrict__ out) {
    __shared__ float ws[KCQ * O4];
    __shared__ float xs[BB][KCQ + 1];
    int n = blockIdx.x, t = threadIdx.x;
    // vectorized fp16 weight load: 3264 halves = 408 uint4
    {
        const uint4* wp4 = (const uint4*)&g_Wh[(size_t)n * (KCQ * O4)];
        for (int l = t; l < 408; l += 256) {
            uint4 v = wp4[l];
            const __half* h = (const __half*)&v;
#pragma unroll
            for (int k = 0; k < 8; k++) ws[l * 8 + k] = __half2float(h[k]);
        }
    }
    for (int l = t; l < BB * KCQ; l += 256) {
        int b = l / KCQ, kc = l % KCQ;
        int k = kc / CC, c = kc % CC;
        float v;
        if (k == 0)      v = x[(size_t)(b * NN + n) * CC + c];
        else if (k == 1) v = g_Y1[(size_t)n * NCP + b * CC + c];
        else             v = g_Y2[(size_t)n * NCP + b * CC + c];
        xs[b][kc] = v;
    }
    __syncthreads();
    {
        int o = t & 63, bq = t >> 6;
        int b0 = bq * 4;
        float a0 = 0.f, a1 = 0.f, a2 = 0.f, a3 = 0.f;
        for (int kc = 0; kc < KCQ; kc++) {
            float w = ws[kc * O4 + o];
            a0 += xs[b0 + 0][kc] * w;
            a1 += xs[b0 + 1][kc] * w;
            a2 += xs[b0 + 2][kc] * w;
            a3 += xs[b0 + 3][kc] * w;
        }
        float bi = g_bias[n * OO + o];
        out[(size_t)((b0 + 0) * NN + n) * OO + o] = a0 + bi;
        out[(size_t)((b0 + 1) * NN + n) * OO + o] = a1 + bi;
        out[(size_t)((b0 + 2) * NN + n) * OO + o] = a2 + bi;
        out[(size_t)((b0 + 3) * NN + n) * OO + o] = a3 + bi;
    }
    if (t < 192) {
        int j = t, o;
        int q = 0; float zr = 0.f, gb = 0.f, wwtv = 0.f, wwsv = 0.f;
        if (j < 32) {
            int k = n * 32 + j;
            q = k / NN; int m = k - q * NN;
            zr = g_rsum[m]; gb = gnnb[m];
            o = 64 + j;
        } else if (j < 160) {
            wwtv = g_wwt[n * O2 + (j - 32)];
            o = 96 + (j - 32);
        } else {
            wwsv = g_wws[n * O8 + (j - 160)];
            o = 224 + (j - 160);
        }
        float bi = g_bias[n * OO + o];
#pragma unroll
        for (int b = 0; b < BB; b++) {
            float v;
            if (j < 32)       v = fmaxf(zin[b * 32 + q] * zr + gb, 0.f);
            else if (j < 160) v = g_xw[b * NN + n] * wwtv;
            else              v = g_xm[n * BB + b] * wwsv;
            out[(size_t)(b * NN + n) * OO + o] = v + bi;
        }
    }
}

// ---------------- launch ----------------
extern "C" void kernel_launch(void* const* d_in, const int* in_sizes, int n_in,
                              void* d_out, int out_size) {
    const float* x     = (const float*)d_in[0];
    const float* xwin  = (const float*)d_in[1];
    const float* ne    = (const float*)d_in[2];
    const int*   fixed = (const int*)  d_in[3];
    const float* adj   = (const float*)d_in[4];
    const int*   stay  = (const int*)  d_in[5];
    const int*   jump  = (const int*)  d_in[6];
    const float* zin   = (const float*)d_in[7];
    const float* hodge = (const float*)d_in[8];
    const float* xew   = (const float*)d_in[9];
    const float* inc   = (const float*)d_in[10];
    const float* wp    = (const float*)d_in[11];
    const float* wwsp  = (const float*)d_in[12];
    const float* wwtp  = (const float*)d_in[13];
    const float* bp    = (const float*)d_in[14];
    const float* Tp    = (const float*)d_in[15];
    const float* lw    = (const float*)d_in[16];
    const float* lb    = (const float*)d_in[17];
    const float* gw    = (const float*)d_in[18];
    const float* gnnb  = (const float*)d_in[19];
    const int*   bidx  = (const int*)  d_in[20];
    float* out = (float*)d_out;
    int nb = in_sizes[20];   // NB = 3

    cudaFuncSetAttribute(kGemmMMA, cudaFuncAttributeMaxDynamicSharedMemorySize, GEMM_SMEM);

    // order chosen so launch #4 (the ncu capture slot) is kS0Softmax
    kPrep<<<NN, 256>>>(ne, bp, wwsp, wwtp, gw, xwin, Tp, x, xew, bidx, lw, lb, jump);
    kWeights<<<dim3(13, 63), 256>>>(ne, wp);
    kH2<<<dim3(24, 12), 128>>>(hodge);
    kS0Softmax<<<500, 256>>>(ne, adj, stay, fixed);
    kColDivH<<<256, 256>>>(fixed);           // dead on softmax path
    kGemmMMA<<<dim3(32, 5), 256, GEMM_SMEM>>>(0);
    kGemmMMA<<<dim3(32, 5), 256, GEMM_SMEM>>>(1);
    kH3<<<125, 256>>>(inc, nb);
    kOut<<<NN, 256>>>(x, zin, gnnb, out);
}